// round 3
// baseline (speedup 1.0000x reference)
#include <cuda_runtime.h>
#include <cuda_fp16.h>
#include <math.h>

#define D      64
#define CAP    128           // max in-degree slots (Poisson(32): P(>=128) ~ e^-81)
#define MAXN   100000
#define MAXB   1024

// ---------------- static device scratch ----------------
__device__ __half2 g_h0[MAXN * 32];       // fp16 node features, ping
__device__ __half2 g_h1[MAXN * 32];       // fp16 node features, pong
__device__ float   g_agg32[MAXN * D];     // fp32 aggregation result (pre-transform)
__device__ float   g_out32[MAXN * D];     // fp32 final features (for Set2Set r)
__device__ int     g_cnt[MAXN];
__device__ int     g_csr_row[MAXN * CAP];
__device__ float   g_csr_w[MAXN * CAP];
__device__ float   g_dinv[MAXN];
__device__ float   g_dinv2[MAXN];
__device__ float   g_e[MAXN];
__device__ int     g_start[MAXB];
__device__ float   g_hl[MAXB * D];
__device__ float   g_cl[MAXB * D];
__device__ float   g_qstar[MAXB * 2 * D];

__device__ __forceinline__ float sigmoidf(float x) { return 1.0f / (1.0f + expf(-x)); }

// ---------------- build phase ----------------
__global__ void k_zero_cnt(int N) {
    int i = blockIdx.x * blockDim.x + threadIdx.x;
    if (i < N) g_cnt[i] = 0;
}

__global__ void k_build(const int* __restrict__ ei, int E) {
    int e = blockIdx.x * blockDim.x + threadIdx.x;
    if (e >= E) return;
    int r = ei[e];
    int c = ei[E + e];
    int slot = atomicAdd(&g_cnt[c], 1);
    if (slot < CAP) g_csr_row[c * CAP + slot] = r;
}

__global__ void k_dinv(int N) {
    int n = blockIdx.x * blockDim.x + threadIdx.x;
    if (n >= N) return;
    float deg = (float)(g_cnt[n] + 1);
    float d = rsqrtf(deg);
    g_dinv[n] = d;
    g_dinv2[n] = d * d;
}

// warp per node; only touch the first cnt slots
__global__ void k_weights(int N) {
    int w = (blockIdx.x * blockDim.x + threadIdx.x) >> 5;
    if (w >= N) return;
    int lane = threadIdx.x & 31;
    int cnt = g_cnt[w]; if (cnt > CAP) cnt = CAP;
    float dn = g_dinv[w];
    for (int s = lane; s < cnt; s += 32) {
        g_csr_w[w * CAP + s] = g_dinv[g_csr_row[w * CAP + s]] * dn;
    }
}

// out0 = relu(x @ W0 + b0) -> fp16 ping buffer
__global__ void k_init_feat(const float* __restrict__ x, const float* __restrict__ W0,
                            const float* __restrict__ b0, int N) {
    int idx = blockIdx.x * blockDim.x + threadIdx.x;
    if (idx >= N * 32) return;
    int n = idx >> 5, p = idx & 31;
    int c0 = 2 * p;
    float a0 = b0[c0], a1 = b0[c0 + 1];
    const float* xr = x + n * 15;
#pragma unroll
    for (int k = 0; k < 15; k++) {
        float xv = xr[k];
        a0 += xv * W0[k * D + c0];
        a1 += xv * W0[k * D + c0 + 1];
    }
    a0 = fmaxf(a0, 0.0f);
    a1 = fmaxf(a1, 0.0f);
    g_h0[idx] = __floats2half2_rn(a0, a1);
}

// ---------------- aggregation of RAW features (fp16 gather, fp32 accum) ----------------
// agg32[n] = sum_edges w*src[row] + dinv2[n]*src[n]
__global__ void k_agg(int flip, int N) {
    const __half2* __restrict__ src = flip ? g_h1 : g_h0;
    int w = (blockIdx.x * blockDim.x + threadIdx.x) >> 5;
    if (w >= N) return;
    int lane = threadIdx.x & 31;
    int cnt = g_cnt[w]; if (cnt > CAP) cnt = CAP;
    const int*   rows = &g_csr_row[w * CAP];
    const float* wts  = &g_csr_w[w * CAP];
    float ax = 0.f, ay = 0.f, bx = 0.f, by = 0.f;
    int s = 0;
    for (; s + 4 <= cnt; s += 4) {
        int   r0 = rows[s],   r1 = rows[s+1], r2 = rows[s+2], r3 = rows[s+3];
        float w0 = wts[s],    w1 = wts[s+1],  w2 = wts[s+2],  w3 = wts[s+3];
        float2 h0 = __half22float2(src[r0 * 32 + lane]);
        float2 h1 = __half22float2(src[r1 * 32 + lane]);
        float2 h2 = __half22float2(src[r2 * 32 + lane]);
        float2 h3 = __half22float2(src[r3 * 32 + lane]);
        ax += w0 * h0.x; ay += w0 * h0.y;
        bx += w1 * h1.x; by += w1 * h1.y;
        ax += w2 * h2.x; ay += w2 * h2.y;
        bx += w3 * h3.x; by += w3 * h3.y;
    }
    for (; s < cnt; s++) {
        int r0 = rows[s]; float w0 = wts[s];
        float2 h0 = __half22float2(src[r0 * 32 + lane]);
        ax += w0 * h0.x; ay += w0 * h0.y;
    }
    float d2 = g_dinv2[w];
    float2 hs = __half22float2(src[w * 32 + lane]);
    ax += bx + d2 * hs.x;
    ay += by + d2 * hs.y;
    *(float2*)&g_agg32[(size_t)w * D + lane * 2] = make_float2(ax, ay);
}

// ---------------- transform: dst = relu(agg32 @ Wc + bc) -> fp16 (+fp32 on last) ----
__global__ void k_gemm_relu(const float* __restrict__ W, const float* __restrict__ bc,
                            int N, int flip, int writeF32) {
    __half2* __restrict__ dst = flip ? g_h0 : g_h1;   // write the other buffer
    __shared__ float xs[64][68];
    __shared__ float ws[64][64];
    __shared__ float bcs[64];
    int t = threadIdx.x;           // 256 threads
    int base = blockIdx.x * 64;

    if (t < 64) bcs[t] = bc[t];
    for (int i = t; i < 1024; i += 256) {
        int row = i >> 4, c4 = (i & 15) << 2;
        *(float4*)&ws[row][c4] = *(const float4*)&W[row * 64 + c4];
        int gr = base + row;
        float4 v = make_float4(0.f, 0.f, 0.f, 0.f);
        if (gr < N) v = *(const float4*)&g_agg32[(size_t)gr * 64 + c4];
        *(float4*)&xs[row][c4] = v;
    }
    __syncthreads();

    int rr = t >> 4;
    int cc = t & 15;
    float4 a0 = {0,0,0,0}, a1 = {0,0,0,0}, a2 = {0,0,0,0}, a3 = {0,0,0,0};
#pragma unroll 16
    for (int k = 0; k < 64; k++) {
        float4 w = *(float4*)&ws[k][cc * 4];
        float x0 = xs[rr * 4 + 0][k];
        float x1 = xs[rr * 4 + 1][k];
        float x2 = xs[rr * 4 + 2][k];
        float x3 = xs[rr * 4 + 3][k];
        a0.x += x0 * w.x; a0.y += x0 * w.y; a0.z += x0 * w.z; a0.w += x0 * w.w;
        a1.x += x1 * w.x; a1.y += x1 * w.y; a1.z += x1 * w.z; a1.w += x1 * w.w;
        a2.x += x2 * w.x; a2.y += x2 * w.y; a2.z += x2 * w.z; a2.w += x2 * w.w;
        a3.x += x3 * w.x; a3.y += x3 * w.y; a3.z += x3 * w.z; a3.w += x3 * w.w;
    }
    float4 bv = *(float4*)&bcs[cc * 4];
    float4 acc[4] = {a0, a1, a2, a3};
#pragma unroll
    for (int q = 0; q < 4; q++) {
        int gr = base + rr * 4 + q;
        if (gr >= N) break;
        float4 a = acc[q];
        a.x = fmaxf(a.x + bv.x, 0.f);
        a.y = fmaxf(a.y + bv.y, 0.f);
        a.z = fmaxf(a.z + bv.z, 0.f);
        a.w = fmaxf(a.w + bv.w, 0.f);
        __half2 pk2[2];
        pk2[0] = __floats2half2_rn(a.x, a.y);
        pk2[1] = __floats2half2_rn(a.z, a.w);
        *(uint2*)&dst[(size_t)gr * 32 + cc * 2] = *(uint2*)pk2;
        if (writeF32) *(float4*)&g_out32[(size_t)gr * 64 + cc * 4] = a;
    }
}

// ---------------- Set2Set ----------------
__global__ void k_start_init(int B, int N) {
    int b = blockIdx.x * blockDim.x + threadIdx.x;
    if (b < B) g_start[b] = N;
}

__global__ void k_boundary(const int* __restrict__ batch, int N) {
    int n = blockIdx.x * blockDim.x + threadIdx.x;
    if (n >= N) return;
    int bn = batch[n];
    if (n == 0 || batch[n - 1] != bn) g_start[bn] = n;
}

__global__ void k_zero_state(int B) {
    int i = blockIdx.x * blockDim.x + threadIdx.x;
    int nd = B * D;
    if (i < nd) { g_hl[i] = 0.f; }
    else if (i < 2 * nd) { g_cl[i - nd] = 0.f; }
    else if (i < 4 * nd) { g_qstar[i - 2 * nd] = 0.f; }
}

__global__ void k_gates(const float* __restrict__ Wih, const float* __restrict__ Whh,
                        const float* __restrict__ bih, const float* __restrict__ bhh) {
    int b = blockIdx.x, j = threadIdx.x;  // 64 threads
    __shared__ float qs[128];
    __shared__ float hl[64];
    qs[j]      = g_qstar[b * 128 + j];
    qs[j + 64] = g_qstar[b * 128 + 64 + j];
    hl[j]      = g_hl[b * 64 + j];
    __syncthreads();

    float gate[4];
#pragma unroll
    for (int gg = 0; gg < 4; gg++) {
        int row = gg * 64 + j;
        float acc = bih[row] + bhh[row];
        const float4* wr = (const float4*)&Wih[row * 128];
#pragma unroll
        for (int k = 0; k < 32; k++) {
            float4 w4 = wr[k];
            acc += qs[4*k+0] * w4.x + qs[4*k+1] * w4.y + qs[4*k+2] * w4.z + qs[4*k+3] * w4.w;
        }
        const float4* hr = (const float4*)&Whh[row * 64];
#pragma unroll
        for (int k = 0; k < 16; k++) {
            float4 w4 = hr[k];
            acc += hl[4*k+0] * w4.x + hl[4*k+1] * w4.y + hl[4*k+2] * w4.z + hl[4*k+3] * w4.w;
        }
        gate[gg] = acc;
    }
    float ig = sigmoidf(gate[0]);
    float fg = sigmoidf(gate[1]);
    float gv = tanhf(gate[2]);
    float og = sigmoidf(gate[3]);
    float cv = fg * g_cl[b * 64 + j] + ig * gv;
    float hv = og * tanhf(cv);
    g_cl[b * 64 + j] = cv;
    g_hl[b * 64 + j] = hv;
}

// e[n] = dot(out_fp16[n], q[batch[n]])
__global__ void k_e(const int* __restrict__ batch, int N) {
    int w = (blockIdx.x * blockDim.x + threadIdx.x) >> 5;
    if (w >= N) return;
    int lane = threadIdx.x & 31;
    int b = batch[w];
    float2 ov = __half22float2(g_h0[(size_t)w * 32 + lane]);
    float2 qv = *(const float2*)&g_hl[(size_t)b * 64 + lane * 2];
    float s = ov.x * qv.x + ov.y * qv.y;
#pragma unroll
    for (int o = 16; o; o >>= 1) s += __shfl_xor_sync(0xffffffffu, s, o);
    if (lane == 0) g_e[w] = s;
}

__global__ void k_attn(const int* __restrict__ batch, int N) {
    int b = blockIdx.x, tid = threadIdx.x;  // 64 threads
    __shared__ float red[64];
    __shared__ float coeff[64];
    __shared__ float m_s, denom_s;
    int st = g_start[b];

    // phase 1: max
    float local = -INFINITY;
    for (int n = st + tid; n < N; n += 64) {
        if (batch[n] != b) break;
        local = fmaxf(local, g_e[n]);
    }
    red[tid] = local;
    __syncthreads();
    if (tid < 32) {
        float v = fmaxf(red[tid], red[tid + 32]);
#pragma unroll
        for (int o = 16; o; o >>= 1) v = fmaxf(v, __shfl_xor_sync(0xffffffffu, v, o));
        if (tid == 0) m_s = v;
    }
    __syncthreads();
    float m = m_s;

    // phase 2: denom; cache a_num back into g_e
    float ls = 0.f;
    for (int n = st + tid; n < N; n += 64) {
        if (batch[n] != b) break;
        float a = expf(g_e[n] - m);
        g_e[n] = a;
        ls += a;
    }
    red[tid] = ls;
    __syncthreads();
    if (tid < 32) {
        float v = red[tid] + red[tid + 32];
#pragma unroll
        for (int o = 16; o; o >>= 1) v += __shfl_xor_sync(0xffffffffu, v, o);
        if (tid == 0) denom_s = v;
    }
    __syncthreads();
    float inv = (denom_s > 0.f) ? (1.0f / denom_s) : 0.f;

    // phase 3: r accumulation (fp32 features)
    float rc = 0.f;
    int c = tid;
    for (int base = st; base < N && batch[base] == b; base += 64) {
        int n = base + tid;
        float cf = 0.f;
        if (n < N && batch[n] == b) cf = g_e[n] * inv;
        coeff[tid] = cf;
        __syncthreads();
        int jmax = N - base; if (jmax > 64) jmax = 64;
        for (int j = 0; j < jmax; j++) {
            if (batch[base + j] != b) break;
            rc += coeff[j] * g_out32[(size_t)(base + j) * 64 + c];
        }
        __syncthreads();
    }
    g_qstar[b * 128 + c]      = g_hl[b * 64 + c];
    g_qstar[b * 128 + 64 + c] = rc;
}

__global__ void k_final(const float* __restrict__ W1, const float* __restrict__ b1,
                        const float* __restrict__ W2, const float* __restrict__ b2,
                        float* __restrict__ y) {
    int b = blockIdx.x, t = threadIdx.x;  // 64 threads
    __shared__ float qs[128];
    __shared__ float hid[64];
    qs[t]      = g_qstar[b * 128 + t];
    qs[t + 64] = g_qstar[b * 128 + 64 + t];
    __syncthreads();
    float acc = b1[t];
#pragma unroll 8
    for (int k = 0; k < 128; k++) acc += qs[k] * W1[k * 64 + t];
    hid[t] = fmaxf(acc, 0.f);
    __syncthreads();
    if (t < 12) {
        float a = b2[t];
#pragma unroll 8
        for (int k = 0; k < 64; k++) a += hid[k] * W2[k * 12 + t];
        y[b * 12 + t] = a;
    }
}

// ---------------- launch ----------------
extern "C" void kernel_launch(void* const* d_in, const int* in_sizes, int n_in,
                              void* d_out, int out_size) {
    const float* x     = (const float*)d_in[0];
    const int*   ei    = (const int*)  d_in[1];
    const int*   batch = (const int*)  d_in[2];
    const float* W0    = (const float*)d_in[3];
    const float* b0    = (const float*)d_in[4];
    const float* Wc    = (const float*)d_in[5];
    const float* bc    = (const float*)d_in[6];
    const float* Wih   = (const float*)d_in[7];
    const float* Whh   = (const float*)d_in[8];
    const float* bih   = (const float*)d_in[9];
    const float* bhh   = (const float*)d_in[10];
    const float* W1    = (const float*)d_in[11];
    const float* b1    = (const float*)d_in[12];
    const float* W2    = (const float*)d_in[13];
    const float* b2    = (const float*)d_in[14];
    float* y = (float*)d_out;

    int N = in_sizes[0] / 15;
    int E = in_sizes[1] / 2;
    int B = out_size / 12;

    // ---- build CSR + normalization ----
    k_zero_cnt<<<(N + 255) / 256, 256>>>(N);
    k_build<<<(E + 255) / 256, 256>>>(ei, E);
    k_dinv<<<(N + 255) / 256, 256>>>(N);
    k_weights<<<(N * 32 + 255) / 256, 256>>>(N);
    k_init_feat<<<(N * 32 + 255) / 256, 256>>>(x, W0, b0, N);

    // ---- 6 propagation steps (gather raw -> transform) ----
    for (int s = 0; s < 6; s++) {
        k_agg<<<(N * 32 + 255) / 256, 256>>>(s & 1, N);
        k_gemm_relu<<<(N + 63) / 64, 256>>>(Wc, bc, N, s & 1, (s == 5) ? 1 : 0);
    }

    // ---- Set2Set ----
    k_start_init<<<(B + 255) / 256, 256>>>(B, N);
    k_boundary<<<(N + 255) / 256, 256>>>(batch, N);
    k_zero_state<<<(B * 4 * D + 255) / 256, 256>>>(B);
    for (int s = 0; s < 6; s++) {
        k_gates<<<B, 64>>>(Wih, Whh, bih, bhh);
        k_e<<<(N * 32 + 255) / 256, 256>>>(batch, N);
        k_attn<<<B, 64>>>(batch, N);
    }

    // ---- final MLP ----
    k_final<<<B, 64>>>(W1, b1, W2, b2, y);
}

// round 4
// speedup vs baseline: 1.1017x; 1.1017x over previous
#include <cuda_runtime.h>
#include <cuda_fp16.h>
#include <math.h>

#define D      64
#define CAP    128           // max in-degree slots (Poisson(32): P(>=128) ~ e^-81)
#define MAXN   100000
#define MAXB   1024

// ---------------- static device scratch ----------------
__device__ __half2 g_h0[MAXN * 32];       // fp16 node features, ping
__device__ __half2 g_h1[MAXN * 32];       // fp16 node features, pong
__device__ int     g_cnt[MAXN];
__device__ int     g_csr_row[MAXN * CAP];
__device__ float   g_csr_w[MAXN * CAP];
__device__ float   g_dinv[MAXN];
__device__ float   g_dinv2[MAXN];
__device__ float   g_e[MAXN];
__device__ int     g_start[MAXB];
__device__ int     g_gcnt[MAXB];
__device__ float   g_hl[MAXB * D];
__device__ float   g_cl[MAXB * D];
__device__ float   g_qstar[MAXB * 2 * D];
__device__ float   g_wT[192 * 256];       // transposed [Wih|Whh]: wT[k][out]
__device__ float   g_bsum[256];           // bih + bhh

__device__ __forceinline__ float sigmoidf(float x) { return 1.0f / (1.0f + expf(-x)); }

// ---------------- init / build ----------------
// zero cnt, gcnt, hl, cl, qstar; start = N
__global__ void k_zero(int N, int B) {
    int i = blockIdx.x * blockDim.x + threadIdx.x;
    if (i < N) g_cnt[i] = 0;
    if (i < B) { g_start[i] = N; g_gcnt[i] = 0; }
    if (i < B * D) { g_hl[i] = 0.f; g_cl[i] = 0.f; }
    if (i < B * 2 * D) g_qstar[i] = 0.f;
}

__global__ void k_build(const int* __restrict__ ei, int E) {
    int e = blockIdx.x * blockDim.x + threadIdx.x;
    if (e >= E) return;
    int r = ei[e];
    int c = ei[E + e];
    int slot = atomicAdd(&g_cnt[c], 1);
    if (slot < CAP) g_csr_row[c * CAP + slot] = r;
}

__global__ void k_dinv(int N) {
    int n = blockIdx.x * blockDim.x + threadIdx.x;
    if (n >= N) return;
    float deg = (float)(g_cnt[n] + 1);
    float d = rsqrtf(deg);
    g_dinv[n] = d;
    g_dinv2[n] = d * d;
}

__global__ void k_weights(int N) {
    int w = (blockIdx.x * blockDim.x + threadIdx.x) >> 5;
    if (w >= N) return;
    int lane = threadIdx.x & 31;
    int cnt = g_cnt[w]; if (cnt > CAP) cnt = CAP;
    float dn = g_dinv[w];
    for (int s = lane; s < cnt; s += 32) {
        g_csr_w[w * CAP + s] = g_dinv[g_csr_row[w * CAP + s]] * dn;
    }
}

// out0 = relu(x @ W0 + b0) -> fp16 ping buffer
__global__ void k_init_feat(const float* __restrict__ x, const float* __restrict__ W0,
                            const float* __restrict__ b0, int N) {
    int idx = blockIdx.x * blockDim.x + threadIdx.x;
    if (idx >= N * 32) return;
    int n = idx >> 5, p = idx & 31;
    int c0 = 2 * p;
    float a0 = b0[c0], a1 = b0[c0 + 1];
    const float* xr = x + n * 15;
#pragma unroll
    for (int k = 0; k < 15; k++) {
        float xv = xr[k];
        a0 += xv * W0[k * D + c0];
        a1 += xv * W0[k * D + c0 + 1];
    }
    g_h0[idx] = __floats2half2_rn(fmaxf(a0, 0.f), fmaxf(a1, 0.f));
}

// transpose LSTM weights: wT[k][o] = k<128 ? Wih[o][k] : Whh[o][k-128]; bsum
__global__ void k_wT(const float* __restrict__ Wih, const float* __restrict__ Whh,
                     const float* __restrict__ bih, const float* __restrict__ bhh) {
    int idx = blockIdx.x * blockDim.x + threadIdx.x;
    if (idx >= 192 * 256) return;
    int k = idx >> 8, o = idx & 255;
    float v = (k < 128) ? Wih[o * 128 + k] : Whh[o * 64 + (k - 128)];
    g_wT[k * 256 + o] = v;
    if (k == 0) g_bsum[o] = bih[o] + bhh[o];
}

__global__ void k_boundary(const int* __restrict__ batch, int N) {
    int n = blockIdx.x * blockDim.x + threadIdx.x;
    if (n >= N) return;
    int bn = batch[n];
    if (n == 0 || batch[n - 1] != bn) g_start[bn] = n;
    atomicAdd(&g_gcnt[bn], 1);
}

// ---------------- fused propagation: gather(fp16) -> GEMM(+bias,relu) -> fp16 ----
__global__ void k_prop(const float* __restrict__ W, const float* __restrict__ bc,
                       int N, int flip) {
    const __half2* __restrict__ src = flip ? g_h1 : g_h0;
    __half2*       __restrict__ dst = flip ? g_h0 : g_h1;
    __shared__ float xs[64][68];
    __shared__ float ws[64][64];
    __shared__ float bcs[64];
    int t = threadIdx.x;           // 256 threads
    int base = blockIdx.x * 64;
    int wrp = t >> 5, lane = t & 31;

    if (t < 64) bcs[t] = bc[t];
    // load W (64x64 floats = 1024 float4)
    for (int i = t; i < 1024; i += 256) {
        int row = i >> 4, c4 = (i & 15) << 2;
        *(float4*)&ws[row][c4] = *(const float4*)&W[row * 64 + c4];
    }

    // gather: warp wrp handles local rows wrp*8 .. wrp*8+7
#pragma unroll 1
    for (int q = 0; q < 8; q++) {
        int row = wrp * 8 + q;
        int n = base + row;
        float ax = 0.f, ay = 0.f, bx = 0.f, by = 0.f;
        if (n < N) {
            int cnt = g_cnt[n]; if (cnt > CAP) cnt = CAP;
            const int*   rows = &g_csr_row[n * CAP];
            const float* wts  = &g_csr_w[n * CAP];
            int s = 0;
            for (; s + 4 <= cnt; s += 4) {
                int   r0 = rows[s],   r1 = rows[s+1], r2 = rows[s+2], r3 = rows[s+3];
                float w0 = wts[s],    w1 = wts[s+1],  w2 = wts[s+2],  w3 = wts[s+3];
                float2 h0 = __half22float2(src[r0 * 32 + lane]);
                float2 h1 = __half22float2(src[r1 * 32 + lane]);
                float2 h2 = __half22float2(src[r2 * 32 + lane]);
                float2 h3 = __half22float2(src[r3 * 32 + lane]);
                ax += w0 * h0.x; ay += w0 * h0.y;
                bx += w1 * h1.x; by += w1 * h1.y;
                ax += w2 * h2.x; ay += w2 * h2.y;
                bx += w3 * h3.x; by += w3 * h3.y;
            }
            for (; s < cnt; s++) {
                int r0 = rows[s]; float w0 = wts[s];
                float2 h0 = __half22float2(src[r0 * 32 + lane]);
                ax += w0 * h0.x; ay += w0 * h0.y;
            }
            float d2 = g_dinv2[n];
            float2 hs = __half22float2(src[n * 32 + lane]);
            ax += bx + d2 * hs.x;
            ay += by + d2 * hs.y;
        }
        *(float2*)&xs[row][lane * 2] = make_float2(ax, ay);
    }
    __syncthreads();

    // GEMM 64x64 @ 64x64, thread tile 4x4
    int rr = t >> 4;
    int cc = t & 15;
    float4 a0 = {0,0,0,0}, a1 = {0,0,0,0}, a2 = {0,0,0,0}, a3 = {0,0,0,0};
#pragma unroll 16
    for (int k = 0; k < 64; k++) {
        float4 w = *(float4*)&ws[k][cc * 4];
        float x0 = xs[rr * 4 + 0][k];
        float x1 = xs[rr * 4 + 1][k];
        float x2 = xs[rr * 4 + 2][k];
        float x3 = xs[rr * 4 + 3][k];
        a0.x += x0 * w.x; a0.y += x0 * w.y; a0.z += x0 * w.z; a0.w += x0 * w.w;
        a1.x += x1 * w.x; a1.y += x1 * w.y; a1.z += x1 * w.z; a1.w += x1 * w.w;
        a2.x += x2 * w.x; a2.y += x2 * w.y; a2.z += x2 * w.z; a2.w += x2 * w.w;
        a3.x += x3 * w.x; a3.y += x3 * w.y; a3.z += x3 * w.z; a3.w += x3 * w.w;
    }
    float4 bv = *(float4*)&bcs[cc * 4];
    float4 acc[4] = {a0, a1, a2, a3};
#pragma unroll
    for (int q = 0; q < 4; q++) {
        int gr = base + rr * 4 + q;
        if (gr >= N) break;
        float4 a = acc[q];
        a.x = fmaxf(a.x + bv.x, 0.f);
        a.y = fmaxf(a.y + bv.y, 0.f);
        a.z = fmaxf(a.z + bv.z, 0.f);
        a.w = fmaxf(a.w + bv.w, 0.f);
        __half2 pk2[2];
        pk2[0] = __floats2half2_rn(a.x, a.y);
        pk2[1] = __floats2half2_rn(a.z, a.w);
        *(uint2*)&dst[(size_t)gr * 32 + cc * 2] = *(uint2*)pk2;
    }
}

// ---------------- Set2Set ----------------
// gates GEMM: 16 graphs per block, thread t = output row (gate*64+j)
__global__ void k_gates(int B) {
    int t = threadIdx.x;   // 256
    int gb = blockIdx.x * 16;
    __shared__ float xs[16][193];
    for (int id = t; id < 16 * 192; id += 256) {
        int g = id / 192, k = id % 192;
        int gg = gb + g;
        float v = 0.f;
        if (gg < B) v = (k < 128) ? g_qstar[gg * 128 + k] : g_hl[gg * 64 + (k - 128)];
        xs[g][k] = v;
    }
    __syncthreads();

    float acc[16];
#pragma unroll
    for (int g = 0; g < 16; g++) acc[g] = 0.f;
#pragma unroll 4
    for (int k = 0; k < 192; k++) {
        float wv = g_wT[k * 256 + t];
#pragma unroll
        for (int g = 0; g < 16; g++) acc[g] += xs[g][k] * wv;
    }
    __shared__ float gsh[256][17];
    float bsum = g_bsum[t];
#pragma unroll
    for (int g = 0; g < 16; g++) gsh[t][g] = acc[g] + bsum;
    __syncthreads();

    if (t < 64) {
        int j = t;
        for (int g = 0; g < 16; g++) {
            int gg = gb + g;
            if (gg >= B) break;
            float ig = sigmoidf(gsh[       j][g]);
            float fg = sigmoidf(gsh[ 64 + j][g]);
            float gv = tanhf   (gsh[128 + j][g]);
            float og = sigmoidf(gsh[192 + j][g]);
            int gi = gg * 64 + j;
            float cv = fg * g_cl[gi] + ig * gv;
            g_cl[gi] = cv;
            g_hl[gi] = og * tanhf(cv);
        }
    }
}

// attention: per-graph block of 256 threads; computes e, softmax, r, q_star
__global__ void k_attn(int N) {
    int b = blockIdx.x, tid = threadIdx.x;
    int wrp = tid >> 5, lane = tid & 31;
    int st = g_start[b];
    int cnt = g_gcnt[b];
    __shared__ float red[256];
    __shared__ float m_s, denom_s;

    // phase 0: e[n] = dot(feat[n], h_l[b])
    float2 qv = *(const float2*)&g_hl[b * 64 + lane * 2];
    for (int i = wrp; i < cnt; i += 8) {
        int n = st + i;
        float2 ov = __half22float2(g_h0[(size_t)n * 32 + lane]);
        float s = ov.x * qv.x + ov.y * qv.y;
#pragma unroll
        for (int o = 16; o; o >>= 1) s += __shfl_xor_sync(0xffffffffu, s, o);
        if (lane == 0) g_e[n] = s;
    }
    __syncthreads();

    // phase 1: max
    float local = -INFINITY;
    for (int i = tid; i < cnt; i += 256) local = fmaxf(local, g_e[st + i]);
    red[tid] = local;
    __syncthreads();
    if (tid < 128) red[tid] = fmaxf(red[tid], red[tid + 128]);
    __syncthreads();
    if (tid < 64) red[tid] = fmaxf(red[tid], red[tid + 64]);
    __syncthreads();
    if (tid < 32) {
        float v = fmaxf(red[tid], red[tid + 32]);
#pragma unroll
        for (int o = 16; o; o >>= 1) v = fmaxf(v, __shfl_xor_sync(0xffffffffu, v, o));
        if (tid == 0) m_s = v;
    }
    __syncthreads();
    float m = m_s;

    // phase 2: a = exp(e - m) (cached back to g_e), denom
    float ls = 0.f;
    for (int i = tid; i < cnt; i += 256) {
        float a = expf(g_e[st + i] - m);
        g_e[st + i] = a;
        ls += a;
    }
    red[tid] = ls;
    __syncthreads();
    if (tid < 128) red[tid] += red[tid + 128];
    __syncthreads();
    if (tid < 64) red[tid] += red[tid + 64];
    __syncthreads();
    if (tid < 32) {
        float v = red[tid] + red[tid + 32];
#pragma unroll
        for (int o = 16; o; o >>= 1) v += __shfl_xor_sync(0xffffffffu, v, o);
        if (tid == 0) denom_s = v;
    }
    __syncthreads();
    float inv = (denom_s > 0.f) ? (1.0f / denom_s) : 0.f;

    // phase 3: r = sum a*out  (fp16 features; 4 parallel 64-node groups)
    int grp = tid >> 6, c = tid & 63;
    const __half* featH = (const __half*)g_h0;
    float rc = 0.f;
    __shared__ float coeff[256];
    for (int base = 0; base < cnt; base += 256) {
        int i = base + tid;
        coeff[tid] = (i < cnt) ? g_e[st + i] * inv : 0.f;
        __syncthreads();
        int off = base + grp * 64;
        int lim = cnt - off; if (lim > 64) lim = 64;
        const __half* srcp = featH + (size_t)(st + off) * 64 + c;
        for (int j = 0; j < lim; j++) {
            rc += coeff[grp * 64 + j] * __half2float(srcp[(size_t)j * 64]);
        }
        __syncthreads();
    }
    red[tid] = rc;
    __syncthreads();
    if (tid < 64) {
        float r = red[tid] + red[tid + 64] + red[tid + 128] + red[tid + 192];
        g_qstar[b * 128 + tid]      = g_hl[b * 64 + tid];
        g_qstar[b * 128 + 64 + tid] = r;
    }
}

// y = relu(q_star @ W1 + b1) @ W2 + b2
__global__ void k_final(const float* __restrict__ W1, const float* __restrict__ b1,
                        const float* __restrict__ W2, const float* __restrict__ b2,
                        float* __restrict__ y) {
    int b = blockIdx.x, t = threadIdx.x;  // 64 threads
    __shared__ float qs[128];
    __shared__ float hid[64];
    qs[t]      = g_qstar[b * 128 + t];
    qs[t + 64] = g_qstar[b * 128 + 64 + t];
    __syncthreads();
    float acc = b1[t];
#pragma unroll 8
    for (int k = 0; k < 128; k++) acc += qs[k] * W1[k * 64 + t];
    hid[t] = fmaxf(acc, 0.f);
    __syncthreads();
    if (t < 12) {
        float a = b2[t];
#pragma unroll 8
        for (int k = 0; k < 64; k++) a += hid[k] * W2[k * 12 + t];
        y[b * 12 + t] = a;
    }
}

// ---------------- launch ----------------
extern "C" void kernel_launch(void* const* d_in, const int* in_sizes, int n_in,
                              void* d_out, int out_size) {
    const float* x     = (const float*)d_in[0];
    const int*   ei    = (const int*)  d_in[1];
    const int*   batch = (const int*)  d_in[2];
    const float* W0    = (const float*)d_in[3];
    const float* b0    = (const float*)d_in[4];
    const float* Wc    = (const float*)d_in[5];
    const float* bc    = (const float*)d_in[6];
    const float* Wih   = (const float*)d_in[7];
    const float* Whh   = (const float*)d_in[8];
    const float* bih   = (const float*)d_in[9];
    const float* bhh   = (const float*)d_in[10];
    const float* W1    = (const float*)d_in[11];
    const float* b1    = (const float*)d_in[12];
    const float* W2    = (const float*)d_in[13];
    const float* b2    = (const float*)d_in[14];
    float* y = (float*)d_out;

    int N = in_sizes[0] / 15;
    int E = in_sizes[1] / 2;
    int B = out_size / 12;

    // ---- init + build ----
    int zmax = (N > B * 2 * D) ? N : B * 2 * D;
    k_zero<<<(zmax + 255) / 256, 256>>>(N, B);
    k_build<<<(E + 255) / 256, 256>>>(ei, E);
    k_boundary<<<(N + 255) / 256, 256>>>(batch, N);
    k_wT<<<(192 * 256 + 255) / 256, 256>>>(Wih, Whh, bih, bhh);
    k_dinv<<<(N + 255) / 256, 256>>>(N);
    k_weights<<<(N * 32 + 255) / 256, 256>>>(N);
    k_init_feat<<<(N * 32 + 255) / 256, 256>>>(x, W0, b0, N);

    // ---- 6 fused propagation steps ----
    for (int s = 0; s < 6; s++) {
        k_prop<<<(N + 63) / 64, 256>>>(Wc, bc, N, s & 1);
    }

    // ---- Set2Set: 6 x (gates, attn) ----
    for (int s = 0; s < 6; s++) {
        k_gates<<<(B + 15) / 16, 256>>>(B);
        k_attn<<<B, 256>>>(N);
    }

    // ---- final MLP ----
    k_final<<<B, 64>>>(W1, b1, W2, b2, y);
}

// round 5
// speedup vs baseline: 1.1832x; 1.0740x over previous
#include <cuda_runtime.h>
#include <cuda_fp16.h>
#include <math.h>

#define D      64
#define CAP    128           // max in-degree slots (Poisson(32): P(>=128) ~ e^-81)
#define MAXN   100000
#define MAXB   1024

// ---------------- static device scratch ----------------
__device__ __half2 g_h0[MAXN * 32];       // fp16 node features, ping
__device__ __half2 g_h1[MAXN * 32];       // fp16 node features, pong
__device__ int     g_cnt[MAXN];
__device__ int     g_csr_row[MAXN * CAP];
__device__ float   g_csr_w[MAXN * CAP];
__device__ float   g_dinv[MAXN];
__device__ float   g_dinv2[MAXN];
__device__ float   g_e[MAXN];
__device__ int     g_start[MAXB];
__device__ int     g_gcnt[MAXB];
__device__ float   g_hl[MAXB * D];
__device__ float   g_cl[MAXB * D];
__device__ float   g_qstar[MAXB * 2 * D];
__device__ float   g_wT[192 * 256];       // transposed [Wih|Whh]: wT[k][out]
__device__ float   g_bsum[256];           // bih + bhh

__device__ __forceinline__ float sigmoidf(float x) { return 1.0f / (1.0f + expf(-x)); }

// ---------------- init / build ----------------
__global__ void k_zero(int N, int B) {
    int i = blockIdx.x * blockDim.x + threadIdx.x;
    if (i < N) g_cnt[i] = 0;
    if (i < B) { g_start[i] = N; g_gcnt[i] = 0; }
    if (i < B * D) { g_hl[i] = 0.f; g_cl[i] = 0.f; }
    if (i < B * 2 * D) g_qstar[i] = 0.f;
}

__global__ void k_build(const int* __restrict__ ei, int E) {
    int e = blockIdx.x * blockDim.x + threadIdx.x;
    if (e >= E) return;
    int r = ei[e];
    int c = ei[E + e];
    int slot = atomicAdd(&g_cnt[c], 1);
    if (slot < CAP) g_csr_row[c * CAP + slot] = r;
}

__global__ void k_dinv(int N) {
    int n = blockIdx.x * blockDim.x + threadIdx.x;
    if (n >= N) return;
    float deg = (float)(g_cnt[n] + 1);
    float d = rsqrtf(deg);
    g_dinv[n] = d;
    g_dinv2[n] = d * d;
}

__global__ void k_weights(int N) {
    int w = (blockIdx.x * blockDim.x + threadIdx.x) >> 5;
    if (w >= N) return;
    int lane = threadIdx.x & 31;
    int cnt = g_cnt[w]; if (cnt > CAP) cnt = CAP;
    float dn = g_dinv[w];
    // vectorized: each lane handles a block of 4 slots
    int nblk = (cnt + 3) >> 2;
    for (int bk = lane; bk < nblk; bk += 32) {
        int s = bk * 4;
        if (s + 4 <= cnt) {
            int4 r4 = *(const int4*)&g_csr_row[w * CAP + s];
            float4 o;
            o.x = g_dinv[r4.x] * dn;
            o.y = g_dinv[r4.y] * dn;
            o.z = g_dinv[r4.z] * dn;
            o.w = g_dinv[r4.w] * dn;
            *(float4*)&g_csr_w[w * CAP + s] = o;
        } else {
            for (int t = s; t < cnt; t++)
                g_csr_w[w * CAP + t] = g_dinv[g_csr_row[w * CAP + t]] * dn;
        }
    }
}

// out0 = relu(x @ W0 + b0) -> fp16 ping buffer
__global__ void k_init_feat(const float* __restrict__ x, const float* __restrict__ W0,
                            const float* __restrict__ b0, int N) {
    int idx = blockIdx.x * blockDim.x + threadIdx.x;
    if (idx >= N * 32) return;
    int n = idx >> 5, p = idx & 31;
    int c0 = 2 * p;
    float a0 = b0[c0], a1 = b0[c0 + 1];
    const float* xr = x + n * 15;
#pragma unroll
    for (int k = 0; k < 15; k++) {
        float xv = xr[k];
        a0 += xv * W0[k * D + c0];
        a1 += xv * W0[k * D + c0 + 1];
    }
    g_h0[idx] = __floats2half2_rn(fmaxf(a0, 0.f), fmaxf(a1, 0.f));
}

// transpose LSTM weights
__global__ void k_wT(const float* __restrict__ Wih, const float* __restrict__ Whh,
                     const float* __restrict__ bih, const float* __restrict__ bhh) {
    int idx = blockIdx.x * blockDim.x + threadIdx.x;
    if (idx >= 192 * 256) return;
    int k = idx >> 8, o = idx & 255;
    float v = (k < 128) ? Wih[o * 128 + k] : Whh[o * 64 + (k - 128)];
    g_wT[k * 256 + o] = v;
    if (k == 0) g_bsum[o] = bih[o] + bhh[o];
}

__global__ void k_boundary(const int* __restrict__ batch, int N) {
    int n = blockIdx.x * blockDim.x + threadIdx.x;
    if (n >= N) return;
    int bn = batch[n];
    if (n == 0 || batch[n - 1] != bn) g_start[bn] = n;
    atomicAdd(&g_gcnt[bn], 1);
}

// ---------------- fused propagation: gather(fp16) -> GEMM(+bias,relu) -> fp16 ----
__global__ void k_prop(const float* __restrict__ W, const float* __restrict__ bc,
                       int N, int flip) {
    const __half2* __restrict__ src = flip ? g_h1 : g_h0;
    __half2*       __restrict__ dst = flip ? g_h0 : g_h1;
    __shared__ float xs[64][68];
    __shared__ float ws[64][64];
    __shared__ float bcs[64];
    int t = threadIdx.x;           // 256 threads
    int base = blockIdx.x * 64;
    int wrp = t >> 5, lane = t & 31;

    if (t < 64) bcs[t] = bc[t];
    for (int i = t; i < 1024; i += 256) {
        int row = i >> 4, c4 = (i & 15) << 2;
        *(float4*)&ws[row][c4] = *(const float4*)&W[row * 64 + c4];
    }

    // gather: warp wrp handles local rows wrp*8 .. wrp*8+7
#pragma unroll 1
    for (int q = 0; q < 8; q++) {
        int row = wrp * 8 + q;
        int n = base + row;
        float ax = 0.f, ay = 0.f, bx = 0.f, by = 0.f;
        float cx = 0.f, cy = 0.f, dx = 0.f, dy = 0.f;
        if (n < N) {
            int cnt = g_cnt[n]; if (cnt > CAP) cnt = CAP;
            const int*   rows = &g_csr_row[n * CAP];
            const float* wts  = &g_csr_w[n * CAP];
            int s = 0;
            // 8-wide unroll: 8 independent gathers in flight
            for (; s + 8 <= cnt; s += 8) {
                int4   ra = *(const int4*)  (rows + s);
                int4   rb = *(const int4*)  (rows + s + 4);
                float4 wa = *(const float4*)(wts  + s);
                float4 wb = *(const float4*)(wts  + s + 4);
                float2 h0 = __half22float2(src[ra.x * 32 + lane]);
                float2 h1 = __half22float2(src[ra.y * 32 + lane]);
                float2 h2 = __half22float2(src[ra.z * 32 + lane]);
                float2 h3 = __half22float2(src[ra.w * 32 + lane]);
                float2 h4 = __half22float2(src[rb.x * 32 + lane]);
                float2 h5 = __half22float2(src[rb.y * 32 + lane]);
                float2 h6 = __half22float2(src[rb.z * 32 + lane]);
                float2 h7 = __half22float2(src[rb.w * 32 + lane]);
                ax += wa.x * h0.x; ay += wa.x * h0.y;
                bx += wa.y * h1.x; by += wa.y * h1.y;
                cx += wa.z * h2.x; cy += wa.z * h2.y;
                dx += wa.w * h3.x; dy += wa.w * h3.y;
                ax += wb.x * h4.x; ay += wb.x * h4.y;
                bx += wb.y * h5.x; by += wb.y * h5.y;
                cx += wb.z * h6.x; cy += wb.z * h6.y;
                dx += wb.w * h7.x; dy += wb.w * h7.y;
            }
            if (s + 4 <= cnt) {
                int4   ra = *(const int4*)  (rows + s);
                float4 wa = *(const float4*)(wts  + s);
                float2 h0 = __half22float2(src[ra.x * 32 + lane]);
                float2 h1 = __half22float2(src[ra.y * 32 + lane]);
                float2 h2 = __half22float2(src[ra.z * 32 + lane]);
                float2 h3 = __half22float2(src[ra.w * 32 + lane]);
                ax += wa.x * h0.x; ay += wa.x * h0.y;
                bx += wa.y * h1.x; by += wa.y * h1.y;
                cx += wa.z * h2.x; cy += wa.z * h2.y;
                dx += wa.w * h3.x; dy += wa.w * h3.y;
                s += 4;
            }
            for (; s < cnt; s++) {
                int r0 = rows[s]; float w0 = wts[s];
                float2 h0 = __half22float2(src[r0 * 32 + lane]);
                ax += w0 * h0.x; ay += w0 * h0.y;
            }
            float d2 = g_dinv2[n];
            float2 hs = __half22float2(src[n * 32 + lane]);
            ax += d2 * hs.x;
            ay += d2 * hs.y;
            ax += bx + cx + dx;
            ay += by + cy + dy;
        }
        *(float2*)&xs[row][lane * 2] = make_float2(ax, ay);
    }
    __syncthreads();

    // GEMM 64x64 @ 64x64, thread tile 4x4
    int rr = t >> 4;
    int cc = t & 15;
    float4 a0 = {0,0,0,0}, a1 = {0,0,0,0}, a2 = {0,0,0,0}, a3 = {0,0,0,0};
#pragma unroll 16
    for (int k = 0; k < 64; k++) {
        float4 w = *(float4*)&ws[k][cc * 4];
        float x0 = xs[rr * 4 + 0][k];
        float x1 = xs[rr * 4 + 1][k];
        float x2 = xs[rr * 4 + 2][k];
        float x3 = xs[rr * 4 + 3][k];
        a0.x += x0 * w.x; a0.y += x0 * w.y; a0.z += x0 * w.z; a0.w += x0 * w.w;
        a1.x += x1 * w.x; a1.y += x1 * w.y; a1.z += x1 * w.z; a1.w += x1 * w.w;
        a2.x += x2 * w.x; a2.y += x2 * w.y; a2.z += x2 * w.z; a2.w += x2 * w.w;
        a3.x += x3 * w.x; a3.y += x3 * w.y; a3.z += x3 * w.z; a3.w += x3 * w.w;
    }
    float4 bv = *(float4*)&bcs[cc * 4];
    float4 acc[4] = {a0, a1, a2, a3};
#pragma unroll
    for (int q = 0; q < 4; q++) {
        int gr = base + rr * 4 + q;
        if (gr >= N) break;
        float4 a = acc[q];
        a.x = fmaxf(a.x + bv.x, 0.f);
        a.y = fmaxf(a.y + bv.y, 0.f);
        a.z = fmaxf(a.z + bv.z, 0.f);
        a.w = fmaxf(a.w + bv.w, 0.f);
        __half2 pk2[2];
        pk2[0] = __floats2half2_rn(a.x, a.y);
        pk2[1] = __floats2half2_rn(a.z, a.w);
        *(uint2*)&dst[(size_t)gr * 32 + cc * 2] = *(uint2*)pk2;
    }
}

// ---------------- Set2Set ----------------
__global__ void k_gates(int B) {
    int t = threadIdx.x;   // 256
    int gb = blockIdx.x * 16;
    __shared__ float xs[16][193];
    for (int id = t; id < 16 * 192; id += 256) {
        int g = id / 192, k = id % 192;
        int gg = gb + g;
        float v = 0.f;
        if (gg < B) v = (k < 128) ? g_qstar[gg * 128 + k] : g_hl[gg * 64 + (k - 128)];
        xs[g][k] = v;
    }
    __syncthreads();

    float acc[16];
#pragma unroll
    for (int g = 0; g < 16; g++) acc[g] = 0.f;
#pragma unroll 4
    for (int k = 0; k < 192; k++) {
        float wv = g_wT[k * 256 + t];
#pragma unroll
        for (int g = 0; g < 16; g++) acc[g] += xs[g][k] * wv;
    }
    __shared__ float gsh[256][17];
    float bsum = g_bsum[t];
#pragma unroll
    for (int g = 0; g < 16; g++) gsh[t][g] = acc[g] + bsum;
    __syncthreads();

    if (t < 64) {
        int j = t;
        for (int g = 0; g < 16; g++) {
            int gg = gb + g;
            if (gg >= B) break;
            float ig = sigmoidf(gsh[       j][g]);
            float fg = sigmoidf(gsh[ 64 + j][g]);
            float gv = tanhf   (gsh[128 + j][g]);
            float og = sigmoidf(gsh[192 + j][g]);
            int gi = gg * 64 + j;
            float cv = fg * g_cl[gi] + ig * gv;
            g_cl[gi] = cv;
            g_hl[gi] = og * tanhf(cv);
        }
    }
}

__global__ void k_attn(int N) {
    int b = blockIdx.x, tid = threadIdx.x;
    int wrp = tid >> 5, lane = tid & 31;
    int st = g_start[b];
    int cnt = g_gcnt[b];
    __shared__ float red[256];
    __shared__ float m_s, denom_s;

    // phase 0: e[n] = dot(feat[n], h_l[b])
    float2 qv = *(const float2*)&g_hl[b * 64 + lane * 2];
    for (int i = wrp; i < cnt; i += 8) {
        int n = st + i;
        float2 ov = __half22float2(g_h0[(size_t)n * 32 + lane]);
        float s = ov.x * qv.x + ov.y * qv.y;
#pragma unroll
        for (int o = 16; o; o >>= 1) s += __shfl_xor_sync(0xffffffffu, s, o);
        if (lane == 0) g_e[n] = s;
    }
    __syncthreads();

    // phase 1: max
    float local = -INFINITY;
    for (int i = tid; i < cnt; i += 256) local = fmaxf(local, g_e[st + i]);
    red[tid] = local;
    __syncthreads();
    if (tid < 128) red[tid] = fmaxf(red[tid], red[tid + 128]);
    __syncthreads();
    if (tid < 64) red[tid] = fmaxf(red[tid], red[tid + 64]);
    __syncthreads();
    if (tid < 32) {
        float v = fmaxf(red[tid], red[tid + 32]);
#pragma unroll
        for (int o = 16; o; o >>= 1) v = fmaxf(v, __shfl_xor_sync(0xffffffffu, v, o));
        if (tid == 0) m_s = v;
    }
    __syncthreads();
    float m = m_s;

    // phase 2: a = exp(e - m), denom
    float ls = 0.f;
    for (int i = tid; i < cnt; i += 256) {
        float a = expf(g_e[st + i] - m);
        g_e[st + i] = a;
        ls += a;
    }
    red[tid] = ls;
    __syncthreads();
    if (tid < 128) red[tid] += red[tid + 128];
    __syncthreads();
    if (tid < 64) red[tid] += red[tid + 64];
    __syncthreads();
    if (tid < 32) {
        float v = red[tid] + red[tid + 32];
#pragma unroll
        for (int o = 16; o; o >>= 1) v += __shfl_xor_sync(0xffffffffu, v, o);
        if (tid == 0) denom_s = v;
    }
    __syncthreads();
    float inv = (denom_s > 0.f) ? (1.0f / denom_s) : 0.f;

    // phase 3: r = sum a*out (fp16 features; 4 parallel 64-node groups)
    int grp = tid >> 6, c = tid & 63;
    const __half* featH = (const __half*)g_h0;
    float rc = 0.f;
    __shared__ float coeff[256];
    for (int base = 0; base < cnt; base += 256) {
        int i = base + tid;
        coeff[tid] = (i < cnt) ? g_e[st + i] * inv : 0.f;
        __syncthreads();
        int off = base + grp * 64;
        int lim = cnt - off; if (lim > 64) lim = 64;
        const __half* srcp = featH + (size_t)(st + off) * 64 + c;
        for (int j = 0; j < lim; j++) {
            rc += coeff[grp * 64 + j] * __half2float(srcp[(size_t)j * 64]);
        }
        __syncthreads();
    }
    red[tid] = rc;
    __syncthreads();
    if (tid < 64) {
        float r = red[tid] + red[tid + 64] + red[tid + 128] + red[tid + 192];
        g_qstar[b * 128 + tid]      = g_hl[b * 64 + tid];
        g_qstar[b * 128 + 64 + tid] = r;
    }
}

__global__ void k_final(const float* __restrict__ W1, const float* __restrict__ b1,
                        const float* __restrict__ W2, const float* __restrict__ b2,
                        float* __restrict__ y) {
    int b = blockIdx.x, t = threadIdx.x;  // 64 threads
    __shared__ float qs[128];
    __shared__ float hid[64];
    qs[t]      = g_qstar[b * 128 + t];
    qs[t + 64] = g_qstar[b * 128 + 64 + t];
    __syncthreads();
    float acc = b1[t];
#pragma unroll 8
    for (int k = 0; k < 128; k++) acc += qs[k] * W1[k * 64 + t];
    hid[t] = fmaxf(acc, 0.f);
    __syncthreads();
    if (t < 12) {
        float a = b2[t];
#pragma unroll 8
        for (int k = 0; k < 64; k++) a += hid[k] * W2[k * 12 + t];
        y[b * 12 + t] = a;
    }
}

// ---------------- launch ----------------
extern "C" void kernel_launch(void* const* d_in, const int* in_sizes, int n_in,
                              void* d_out, int out_size) {
    const float* x     = (const float*)d_in[0];
    const int*   ei    = (const int*)  d_in[1];
    const int*   batch = (const int*)  d_in[2];
    const float* W0    = (const float*)d_in[3];
    const float* b0    = (const float*)d_in[4];
    const float* Wc    = (const float*)d_in[5];
    const float* bc    = (const float*)d_in[6];
    const float* Wih   = (const float*)d_in[7];
    const float* Whh   = (const float*)d_in[8];
    const float* bih   = (const float*)d_in[9];
    const float* bhh   = (const float*)d_in[10];
    const float* W1    = (const float*)d_in[11];
    const float* b1    = (const float*)d_in[12];
    const float* W2    = (const float*)d_in[13];
    const float* b2    = (const float*)d_in[14];
    float* y = (float*)d_out;

    int N = in_sizes[0] / 15;
    int E = in_sizes[1] / 2;
    int B = out_size / 12;

    // ---- init + build ----
    int zmax = (N > B * 2 * D) ? N : B * 2 * D;
    k_zero<<<(zmax + 255) / 256, 256>>>(N, B);
    k_build<<<(E + 255) / 256, 256>>>(ei, E);
    k_boundary<<<(N + 255) / 256, 256>>>(batch, N);
    k_wT<<<(192 * 256 + 255) / 256, 256>>>(Wih, Whh, bih, bhh);
    k_dinv<<<(N + 255) / 256, 256>>>(N);
    k_weights<<<(N * 32 + 255) / 256, 256>>>(N);
    k_init_feat<<<(N * 32 + 255) / 256, 256>>>(x, W0, b0, N);

    // ---- 6 fused propagation steps ----
    for (int s = 0; s < 6; s++) {
        k_prop<<<(N + 63) / 64, 256>>>(Wc, bc, N, s & 1);
    }

    // ---- Set2Set ----
    for (int s = 0; s < 6; s++) {
        k_gates<<<(B + 15) / 16, 256>>>(B);
        k_attn<<<B, 256>>>(N);
    }

    // ---- final MLP ----
    k_final<<<B, 64>>>(W1, b1, W2, b2, y);
}

// round 6
// speedup vs baseline: 1.2877x; 1.0883x over previous
#include <cuda_runtime.h>
#include <cuda_fp16.h>
#include <math.h>

#define D      64
#define CAP    128           // max in-degree slots (Poisson(32): P(>=128) ~ e^-81)
#define MAXN   100000
#define MAXB   1024

// ---------------- static device scratch ----------------
__device__ __half2 g_h0[MAXN * 32];       // fp16 node features (scaled by dinv), ping
__device__ __half2 g_h1[MAXN * 32];       // pong
__device__ int     g_cnt[MAXN];
__device__ int     g_csr_row[MAXN * CAP];
__device__ float   g_dinv[MAXN];
__device__ float   g_e[MAXN];
__device__ int     g_start[MAXB];
__device__ int     g_gcnt[MAXB];
__device__ float   g_hl[MAXB * D];
__device__ float   g_cl[MAXB * D];
__device__ float   g_qstar[MAXB * 2 * D];
__device__ float   g_wT[192 * 256];       // transposed [Wih|Whh]: wT[k][out]
__device__ float   g_bsum[256];           // bih + bhh

__device__ __forceinline__ float sigmoidf(float x) { return 1.0f / (1.0f + expf(-x)); }

// ---------------- init / build ----------------
__global__ void k_zero(int N, int B) {
    int i = blockIdx.x * blockDim.x + threadIdx.x;
    if (i < N) g_cnt[i] = 0;
    if (i < B) { g_start[i] = N; g_gcnt[i] = 0; }
    if (i < B * D) { g_hl[i] = 0.f; g_cl[i] = 0.f; }
    if (i < B * 2 * D) g_qstar[i] = 0.f;
}

__global__ void k_build(const int* __restrict__ ei, int E) {
    int e = blockIdx.x * blockDim.x + threadIdx.x;
    if (e >= E) return;
    int r = ei[e];
    int c = ei[E + e];
    int slot = atomicAdd(&g_cnt[c], 1);
    if (slot < CAP) g_csr_row[c * CAP + slot] = r;
}

__global__ void k_dinv(int N) {
    int n = blockIdx.x * blockDim.x + threadIdx.x;
    if (n >= N) return;
    float deg = (float)(g_cnt[n] + 1);
    g_dinv[n] = rsqrtf(deg);
}

// out0 = dinv * relu(x @ W0 + b0) -> fp16 ping buffer (pre-scaled storage)
__global__ void k_init_feat(const float* __restrict__ x, const float* __restrict__ W0,
                            const float* __restrict__ b0, int N) {
    int idx = blockIdx.x * blockDim.x + threadIdx.x;
    if (idx >= N * 32) return;
    int n = idx >> 5, p = idx & 31;
    int c0 = 2 * p;
    float a0 = b0[c0], a1 = b0[c0 + 1];
    const float* xr = x + n * 15;
#pragma unroll
    for (int k = 0; k < 15; k++) {
        float xv = xr[k];
        a0 += xv * W0[k * D + c0];
        a1 += xv * W0[k * D + c0 + 1];
    }
    float dv = g_dinv[n];
    g_h0[idx] = __floats2half2_rn(dv * fmaxf(a0, 0.f), dv * fmaxf(a1, 0.f));
}

// transpose LSTM weights
__global__ void k_wT(const float* __restrict__ Wih, const float* __restrict__ Whh,
                     const float* __restrict__ bih, const float* __restrict__ bhh) {
    int idx = blockIdx.x * blockDim.x + threadIdx.x;
    if (idx >= 192 * 256) return;
    int k = idx >> 8, o = idx & 255;
    float v = (k < 128) ? Wih[o * 128 + k] : Whh[o * 64 + (k - 128)];
    g_wT[k * 256 + o] = v;
    if (k == 0) g_bsum[o] = bih[o] + bhh[o];
}

__global__ void k_boundary(const int* __restrict__ batch, int N) {
    int n = blockIdx.x * blockDim.x + threadIdx.x;
    if (n >= N) return;
    int bn = batch[n];
    if (n == 0 || batch[n - 1] != bn) g_start[bn] = n;
    atomicAdd(&g_gcnt[bn], 1);
}

// ---------------- fused propagation ----------------
// features stored pre-scaled: f = dinv * out
// agg = sum_in f_r + f_self ; x = dinv * agg ; out = relu(x @ Wc + bc)
// store: last ? out : dinv*out  (fp16)
__global__ void k_prop(const float* __restrict__ W, const float* __restrict__ bc,
                       int N, int flip, int last) {
    const __half2* __restrict__ src = flip ? g_h1 : g_h0;
    __half2*       __restrict__ dst = flip ? g_h0 : g_h1;
    __shared__ float xs[64][68];
    __shared__ float ws[64][64];
    __shared__ float bcs[64];
    int t = threadIdx.x;           // 256 threads
    int base = blockIdx.x * 64;
    int wrp = t >> 5, lane = t & 31;

    if (t < 64) bcs[t] = bc[t];
    for (int i = t; i < 1024; i += 256) {
        int row = i >> 4, c4 = (i & 15) << 2;
        *(float4*)&ws[row][c4] = *(const float4*)&W[row * 64 + c4];
    }

    // gather: warp wrp handles local rows wrp*8 .. wrp*8+7 (weight-free sum)
#pragma unroll 1
    for (int q = 0; q < 8; q++) {
        int row = wrp * 8 + q;
        int n = base + row;
        float ax = 0.f, ay = 0.f, bx = 0.f, by = 0.f;
        float cx = 0.f, cy = 0.f, dx = 0.f, dy = 0.f;
        if (n < N) {
            int cnt = g_cnt[n]; if (cnt > CAP) cnt = CAP;
            const int* rows = &g_csr_row[n * CAP];
            int s = 0;
            for (; s + 8 <= cnt; s += 8) {
                int4 ra = *(const int4*)(rows + s);
                int4 rb = *(const int4*)(rows + s + 4);
                float2 h0 = __half22float2(src[ra.x * 32 + lane]);
                float2 h1 = __half22float2(src[ra.y * 32 + lane]);
                float2 h2 = __half22float2(src[ra.z * 32 + lane]);
                float2 h3 = __half22float2(src[ra.w * 32 + lane]);
                float2 h4 = __half22float2(src[rb.x * 32 + lane]);
                float2 h5 = __half22float2(src[rb.y * 32 + lane]);
                float2 h6 = __half22float2(src[rb.z * 32 + lane]);
                float2 h7 = __half22float2(src[rb.w * 32 + lane]);
                ax += h0.x + h4.x; ay += h0.y + h4.y;
                bx += h1.x + h5.x; by += h1.y + h5.y;
                cx += h2.x + h6.x; cy += h2.y + h6.y;
                dx += h3.x + h7.x; dy += h3.y + h7.y;
            }
            if (s + 4 <= cnt) {
                int4 ra = *(const int4*)(rows + s);
                float2 h0 = __half22float2(src[ra.x * 32 + lane]);
                float2 h1 = __half22float2(src[ra.y * 32 + lane]);
                float2 h2 = __half22float2(src[ra.z * 32 + lane]);
                float2 h3 = __half22float2(src[ra.w * 32 + lane]);
                ax += h0.x; ay += h0.y;
                bx += h1.x; by += h1.y;
                cx += h2.x; cy += h2.y;
                dx += h3.x; dy += h3.y;
                s += 4;
            }
            for (; s < cnt; s++) {
                float2 h0 = __half22float2(src[rows[s] * 32 + lane]);
                ax += h0.x; ay += h0.y;
            }
            float2 hs = __half22float2(src[n * 32 + lane]);
            float dv = g_dinv[n];
            ax = dv * (ax + bx + cx + dx + hs.x);
            ay = dv * (ay + by + cy + dy + hs.y);
        }
        *(float2*)&xs[row][lane * 2] = make_float2(ax, ay);
    }
    __syncthreads();

    // GEMM 64x64 @ 64x64, thread tile 4x4
    int rr = t >> 4;
    int cc = t & 15;
    float4 a0 = {0,0,0,0}, a1 = {0,0,0,0}, a2 = {0,0,0,0}, a3 = {0,0,0,0};
#pragma unroll 16
    for (int k = 0; k < 64; k++) {
        float4 w = *(float4*)&ws[k][cc * 4];
        float x0 = xs[rr * 4 + 0][k];
        float x1 = xs[rr * 4 + 1][k];
        float x2 = xs[rr * 4 + 2][k];
        float x3 = xs[rr * 4 + 3][k];
        a0.x += x0 * w.x; a0.y += x0 * w.y; a0.z += x0 * w.z; a0.w += x0 * w.w;
        a1.x += x1 * w.x; a1.y += x1 * w.y; a1.z += x1 * w.z; a1.w += x1 * w.w;
        a2.x += x2 * w.x; a2.y += x2 * w.y; a2.z += x2 * w.z; a2.w += x2 * w.w;
        a3.x += x3 * w.x; a3.y += x3 * w.y; a3.z += x3 * w.z; a3.w += x3 * w.w;
    }
    float4 bv = *(float4*)&bcs[cc * 4];
    float4 acc[4] = {a0, a1, a2, a3};
#pragma unroll
    for (int q = 0; q < 4; q++) {
        int gr = base + rr * 4 + q;
        if (gr >= N) break;
        float4 a = acc[q];
        a.x = fmaxf(a.x + bv.x, 0.f);
        a.y = fmaxf(a.y + bv.y, 0.f);
        a.z = fmaxf(a.z + bv.z, 0.f);
        a.w = fmaxf(a.w + bv.w, 0.f);
        float sc = last ? 1.0f : g_dinv[gr];
        __half2 pk2[2];
        pk2[0] = __floats2half2_rn(sc * a.x, sc * a.y);
        pk2[1] = __floats2half2_rn(sc * a.z, sc * a.w);
        *(uint2*)&dst[(size_t)gr * 32 + cc * 2] = *(uint2*)pk2;
    }
}

// ---------------- Set2Set ----------------
__global__ void k_gates(int B) {
    int t = threadIdx.x;   // 256
    int gb = blockIdx.x * 16;
    __shared__ float xs[16][193];
    for (int id = t; id < 16 * 192; id += 256) {
        int g = id / 192, k = id % 192;
        int gg = gb + g;
        float v = 0.f;
        if (gg < B) v = (k < 128) ? g_qstar[gg * 128 + k] : g_hl[gg * 64 + (k - 128)];
        xs[g][k] = v;
    }
    __syncthreads();

    float acc[16];
#pragma unroll
    for (int g = 0; g < 16; g++) acc[g] = 0.f;
#pragma unroll 4
    for (int k = 0; k < 192; k++) {
        float wv = g_wT[k * 256 + t];
#pragma unroll
        for (int g = 0; g < 16; g++) acc[g] += xs[g][k] * wv;
    }
    __shared__ float gsh[256][17];
    float bsum = g_bsum[t];
#pragma unroll
    for (int g = 0; g < 16; g++) gsh[t][g] = acc[g] + bsum;
    __syncthreads();

    if (t < 64) {
        int j = t;
        for (int g = 0; g < 16; g++) {
            int gg = gb + g;
            if (gg >= B) break;
            float ig = sigmoidf(gsh[       j][g]);
            float fg = sigmoidf(gsh[ 64 + j][g]);
            float gv = tanhf   (gsh[128 + j][g]);
            float og = sigmoidf(gsh[192 + j][g]);
            int gi = gg * 64 + j;
            float cv = fg * g_cl[gi] + ig * gv;
            g_cl[gi] = cv;
            g_hl[gi] = og * tanhf(cv);
        }
    }
}

__global__ void k_attn(int N) {
    int b = blockIdx.x, tid = threadIdx.x;
    int wrp = tid >> 5, lane = tid & 31;
    int st = g_start[b];
    int cnt = g_gcnt[b];
    __shared__ float red[256];
    __shared__ float m_s, denom_s;

    // phase 0: e[n] = dot(feat[n], h_l[b])
    float2 qv = *(const float2*)&g_hl[b * 64 + lane * 2];
    for (int i = wrp; i < cnt; i += 8) {
        int n = st + i;
        float2 ov = __half22float2(g_h0[(size_t)n * 32 + lane]);
        float s = ov.x * qv.x + ov.y * qv.y;
#pragma unroll
        for (int o = 16; o; o >>= 1) s += __shfl_xor_sync(0xffffffffu, s, o);
        if (lane == 0) g_e[n] = s;
    }
    __syncthreads();

    // phase 1: max
    float local = -INFINITY;
    for (int i = tid; i < cnt; i += 256) local = fmaxf(local, g_e[st + i]);
    red[tid] = local;
    __syncthreads();
    if (tid < 128) red[tid] = fmaxf(red[tid], red[tid + 128]);
    __syncthreads();
    if (tid < 64) red[tid] = fmaxf(red[tid], red[tid + 64]);
    __syncthreads();
    if (tid < 32) {
        float v = fmaxf(red[tid], red[tid + 32]);
#pragma unroll
        for (int o = 16; o; o >>= 1) v = fmaxf(v, __shfl_xor_sync(0xffffffffu, v, o));
        if (tid == 0) m_s = v;
    }
    __syncthreads();
    float m = m_s;

    // phase 2: a = exp(e - m), denom
    float ls = 0.f;
    for (int i = tid; i < cnt; i += 256) {
        float a = expf(g_e[st + i] - m);
        g_e[st + i] = a;
        ls += a;
    }
    red[tid] = ls;
    __syncthreads();
    if (tid < 128) red[tid] += red[tid + 128];
    __syncthreads();
    if (tid < 64) red[tid] += red[tid + 64];
    __syncthreads();
    if (tid < 32) {
        float v = red[tid] + red[tid + 32];
#pragma unroll
        for (int o = 16; o; o >>= 1) v += __shfl_xor_sync(0xffffffffu, v, o);
        if (tid == 0) denom_s = v;
    }
    __syncthreads();
    float inv = (denom_s > 0.f) ? (1.0f / denom_s) : 0.f;

    // phase 3: r = sum a*out (fp16 features; 4 parallel 64-node groups)
    int grp = tid >> 6, c = tid & 63;
    const __half* featH = (const __half*)g_h0;
    float rc = 0.f;
    __shared__ float coeff[256];
    for (int base = 0; base < cnt; base += 256) {
        int i = base + tid;
        coeff[tid] = (i < cnt) ? g_e[st + i] * inv : 0.f;
        __syncthreads();
        int off = base + grp * 64;
        int lim = cnt - off; if (lim > 64) lim = 64;
        const __half* srcp = featH + (size_t)(st + off) * 64 + c;
        for (int j = 0; j < lim; j++) {
            rc += coeff[grp * 64 + j] * __half2float(srcp[(size_t)j * 64]);
        }
        __syncthreads();
    }
    red[tid] = rc;
    __syncthreads();
    if (tid < 64) {
        float r = red[tid] + red[tid + 64] + red[tid + 128] + red[tid + 192];
        g_qstar[b * 128 + tid]      = g_hl[b * 64 + tid];
        g_qstar[b * 128 + 64 + tid] = r;
    }
}

__global__ void k_final(const float* __restrict__ W1, const float* __restrict__ b1,
                        const float* __restrict__ W2, const float* __restrict__ b2,
                        float* __restrict__ y) {
    int b = blockIdx.x, t = threadIdx.x;  // 64 threads
    __shared__ float qs[128];
    __shared__ float hid[64];
    qs[t]      = g_qstar[b * 128 + t];
    qs[t + 64] = g_qstar[b * 128 + 64 + t];
    __syncthreads();
    float acc = b1[t];
#pragma unroll 8
    for (int k = 0; k < 128; k++) acc += qs[k] * W1[k * 64 + t];
    hid[t] = fmaxf(acc, 0.f);
    __syncthreads();
    if (t < 12) {
        float a = b2[t];
#pragma unroll 8
        for (int k = 0; k < 64; k++) a += hid[k] * W2[k * 12 + t];
        y[b * 12 + t] = a;
    }
}

// ---------------- launch ----------------
extern "C" void kernel_launch(void* const* d_in, const int* in_sizes, int n_in,
                              void* d_out, int out_size) {
    const float* x     = (const float*)d_in[0];
    const int*   ei    = (const int*)  d_in[1];
    const int*   batch = (const int*)  d_in[2];
    const float* W0    = (const float*)d_in[3];
    const float* b0    = (const float*)d_in[4];
    const float* Wc    = (const float*)d_in[5];
    const float* bc    = (const float*)d_in[6];
    const float* Wih   = (const float*)d_in[7];
    const float* Whh   = (const float*)d_in[8];
    const float* bih   = (const float*)d_in[9];
    const float* bhh   = (const float*)d_in[10];
    const float* W1    = (const float*)d_in[11];
    const float* b1    = (const float*)d_in[12];
    const float* W2    = (const float*)d_in[13];
    const float* b2    = (const float*)d_in[14];
    float* y = (float*)d_out;

    int N = in_sizes[0] / 15;
    int E = in_sizes[1] / 2;
    int B = out_size / 12;

    // ---- init + build ----
    int zmax = (N > B * 2 * D) ? N : B * 2 * D;
    k_zero<<<(zmax + 255) / 256, 256>>>(N, B);
    k_build<<<(E + 255) / 256, 256>>>(ei, E);
    k_boundary<<<(N + 255) / 256, 256>>>(batch, N);
    k_wT<<<(192 * 256 + 255) / 256, 256>>>(Wih, Whh, bih, bhh);
    k_dinv<<<(N + 255) / 256, 256>>>(N);
    k_init_feat<<<(N * 32 + 255) / 256, 256>>>(x, W0, b0, N);

    // ---- 6 fused propagation steps ----
    for (int s = 0; s < 6; s++) {
        k_prop<<<(N + 63) / 64, 256>>>(Wc, bc, N, s & 1, (s == 5) ? 1 : 0);
    }

    // ---- Set2Set ----
    for (int s = 0; s < 6; s++) {
        k_gates<<<(B + 15) / 16, 256>>>(B);
        k_attn<<<B, 256>>>(N);
    }

    // ---- final MLP ----
    k_final<<<B, 64>>>(W1, b1, W2, b2, y);
}

// round 8
// speedup vs baseline: 1.4461x; 1.1230x over previous
#include <cuda_runtime.h>
#include <cuda_fp16.h>
#include <stdint.h>
#include <math.h>

#define D      64
#define CAP    128           // max in-degree slots (Poisson(32): P(>=128) ~ e^-81)
#define MAXN   100000
#define MAXB   1024

// ---------------- static device scratch ----------------
__device__ __half2 g_h0[MAXN * 32];       // fp16 node features (scaled by dinv), ping
__device__ __half2 g_h1[MAXN * 32];       // pong
__device__ int     g_cnt[MAXN];
__device__ int     g_csr_row[MAXN * CAP];
__device__ float   g_dinv[MAXN];
__device__ float   g_e[MAXN];
__device__ int     g_start[MAXB];
__device__ int     g_gcnt[MAXB];
__device__ float   g_hl[MAXB * D];
__device__ float   g_cl[MAXB * D];
__device__ float   g_qstar[MAXB * 2 * D];
__device__ float   g_wT[192 * 256];       // transposed [Wih|Whh]: wT[k][out]
__device__ float   g_bsum[256];           // bih + bhh

__device__ __forceinline__ float sigmoidf(float x) { return 1.0f / (1.0f + expf(-x)); }

#define LDSM_X4(r0,r1,r2,r3, addr) \
  asm volatile("ldmatrix.sync.aligned.m8n8.x4.shared.b16 {%0,%1,%2,%3}, [%4];" \
    : "=r"(r0), "=r"(r1), "=r"(r2), "=r"(r3) : "r"(addr))

#define LDSM_X4_T(r0,r1,r2,r3, addr) \
  asm volatile("ldmatrix.sync.aligned.m8n8.x4.trans.shared.b16 {%0,%1,%2,%3}, [%4];" \
    : "=r"(r0), "=r"(r1), "=r"(r2), "=r"(r3) : "r"(addr))

#define MMA16816(c0,c1,c2,c3, a0,a1,a2,a3, b0,b1) \
  asm volatile("mma.sync.aligned.m16n8k16.row.col.f32.f16.f16.f32 " \
    "{%0,%1,%2,%3}, {%4,%5,%6,%7}, {%8,%9}, {%0,%1,%2,%3};" \
    : "+f"(c0), "+f"(c1), "+f"(c2), "+f"(c3) \
    : "r"(a0), "r"(a1), "r"(a2), "r"(a3), "r"(b0), "r"(b1))

// ---------------- init / build ----------------
__global__ void k_zero(int N, int B) {
    int i = blockIdx.x * blockDim.x + threadIdx.x;
    if (i < N) g_cnt[i] = 0;
    if (i < B) { g_start[i] = N; g_gcnt[i] = 0; }
    if (i < B * D) { g_hl[i] = 0.f; g_cl[i] = 0.f; }
    if (i < B * 2 * D) g_qstar[i] = 0.f;
}

__global__ void k_build(const int* __restrict__ ei, int E) {
    int e = blockIdx.x * blockDim.x + threadIdx.x;
    if (e >= E) return;
    int r = ei[e];
    int c = ei[E + e];
    int slot = atomicAdd(&g_cnt[c], 1);
    if (slot < CAP) g_csr_row[c * CAP + slot] = r;
}

__global__ void k_dinv(int N) {
    int n = blockIdx.x * blockDim.x + threadIdx.x;
    if (n >= N) return;
    float deg = (float)(g_cnt[n] + 1);
    g_dinv[n] = rsqrtf(deg);
}

// out0 = dinv * relu(x @ W0 + b0) -> fp16 ping buffer (pre-scaled storage)
__global__ void k_init_feat(const float* __restrict__ x, const float* __restrict__ W0,
                            const float* __restrict__ b0, int N) {
    int idx = blockIdx.x * blockDim.x + threadIdx.x;
    if (idx >= N * 32) return;
    int n = idx >> 5, p = idx & 31;
    int c0 = 2 * p;
    float a0 = b0[c0], a1 = b0[c0 + 1];
    const float* xr = x + n * 15;
#pragma unroll
    for (int k = 0; k < 15; k++) {
        float xv = xr[k];
        a0 += xv * W0[k * D + c0];
        a1 += xv * W0[k * D + c0 + 1];
    }
    float dv = g_dinv[n];
    g_h0[idx] = __floats2half2_rn(dv * fmaxf(a0, 0.f), dv * fmaxf(a1, 0.f));
}

// transpose LSTM weights
__global__ void k_wT(const float* __restrict__ Wih, const float* __restrict__ Whh,
                     const float* __restrict__ bih, const float* __restrict__ bhh) {
    int idx = blockIdx.x * blockDim.x + threadIdx.x;
    if (idx >= 192 * 256) return;
    int k = idx >> 8, o = idx & 255;
    float v = (k < 128) ? Wih[o * 128 + k] : Whh[o * 64 + (k - 128)];
    g_wT[k * 256 + o] = v;
    if (k == 0) g_bsum[o] = bih[o] + bhh[o];
}

__global__ void k_boundary(const int* __restrict__ batch, int N) {
    int n = blockIdx.x * blockDim.x + threadIdx.x;
    if (n >= N) return;
    int bn = batch[n];
    if (n == 0 || batch[n - 1] != bn) g_start[bn] = n;
    atomicAdd(&g_gcnt[bn], 1);
}

// ---------------- fused propagation: gather(fp16) -> HMMA GEMM -> fp16 ----
// features pre-scaled: f = dinv*out ; agg = sum f_r + f_self ; x = dinv*agg
// out = relu(x @ Wc + bc) ; store last ? out : dinv*out
__global__ void k_prop(const float* __restrict__ W, const float* __restrict__ bc,
                       int N, int flip, int last) {
    const __half2* __restrict__ src = flip ? g_h1 : g_h0;
    __half2*       __restrict__ dst = flip ? g_h0 : g_h1;
    __shared__ __half xs_h[64][72];    // gathered x tile (fp16), ldmatrix-friendly
    __shared__ __half ws_h[64][72];    // Wc in fp16, row-major [k][n]
    __shared__ float  bcs[64];
    int t = threadIdx.x;               // 256 threads
    int base = blockIdx.x * 64;
    int wrp = t >> 5, lane = t & 31;

    if (t < 64) bcs[t] = bc[t];
    for (int i = t; i < 4096; i += 256)
        ws_h[i >> 6][i & 63] = __float2half(W[i]);

    // gather: warp wrp handles local rows wrp*8 .. wrp*8+7 (weight-free sum)
#pragma unroll 1
    for (int q = 0; q < 8; q++) {
        int row = wrp * 8 + q;
        int n = base + row;
        float ax = 0.f, ay = 0.f, bx = 0.f, by = 0.f;
        float cx = 0.f, cy = 0.f, dx = 0.f, dy = 0.f;
        if (n < N) {
            int cnt = g_cnt[n]; if (cnt > CAP) cnt = CAP;
            const int* rows = &g_csr_row[n * CAP];
            int s = 0;
            for (; s + 8 <= cnt; s += 8) {
                int4 ra = *(const int4*)(rows + s);
                int4 rb = *(const int4*)(rows + s + 4);
                float2 h0 = __half22float2(src[ra.x * 32 + lane]);
                float2 h1 = __half22float2(src[ra.y * 32 + lane]);
                float2 h2 = __half22float2(src[ra.z * 32 + lane]);
                float2 h3 = __half22float2(src[ra.w * 32 + lane]);
                float2 h4 = __half22float2(src[rb.x * 32 + lane]);
                float2 h5 = __half22float2(src[rb.y * 32 + lane]);
                float2 h6 = __half22float2(src[rb.z * 32 + lane]);
                float2 h7 = __half22float2(src[rb.w * 32 + lane]);
                ax += h0.x + h4.x; ay += h0.y + h4.y;
                bx += h1.x + h5.x; by += h1.y + h5.y;
                cx += h2.x + h6.x; cy += h2.y + h6.y;
                dx += h3.x + h7.x; dy += h3.y + h7.y;
            }
            if (s + 4 <= cnt) {
                int4 ra = *(const int4*)(rows + s);
                float2 h0 = __half22float2(src[ra.x * 32 + lane]);
                float2 h1 = __half22float2(src[ra.y * 32 + lane]);
                float2 h2 = __half22float2(src[ra.z * 32 + lane]);
                float2 h3 = __half22float2(src[ra.w * 32 + lane]);
                ax += h0.x; ay += h0.y;
                bx += h1.x; by += h1.y;
                cx += h2.x; cy += h2.y;
                dx += h3.x; dy += h3.y;
                s += 4;
            }
            for (; s < cnt; s++) {
                float2 h0 = __half22float2(src[rows[s] * 32 + lane]);
                ax += h0.x; ay += h0.y;
            }
            float2 hs = __half22float2(src[n * 32 + lane]);
            float dv = g_dinv[n];
            ax = dv * (ax + bx + cx + dx + hs.x);
            ay = dv * (ay + by + cy + dy + hs.y);
        }
        *(__half2*)&xs_h[row][lane * 2] = __floats2half2_rn(ax, ay);
    }
    __syncthreads();

    // ---- HMMA GEMM: C(64x64) = xs_h @ ws_h, warp tile 16x32 ----
    int wr = wrp >> 1;        // row group 0..3 (16 rows each)
    int wc = wrp & 1;         // col group 0..1 (32 cols each)
    int g  = lane >> 2;       // group id 0..7
    int tt = lane & 3;        // thread in group

    float c[4][4];
#pragma unroll
    for (int i = 0; i < 4; i++)
#pragma unroll
        for (int j = 0; j < 4; j++) c[i][j] = 0.f;

    int arow = wr * 16 + ((lane >> 3) & 1) * 8 + (lane & 7);
    int asub = (lane >> 4) * 8;
    int brsub = ((lane >> 3) & 1) * 8 + (lane & 7);
    int bcsub = (lane >> 4) * 8;

#pragma unroll
    for (int kk = 0; kk < 4; kk++) {
        uint32_t a0, a1, a2, a3;
        uint32_t aaddr = (uint32_t)__cvta_generic_to_shared(&xs_h[arow][kk * 16 + asub]);
        LDSM_X4(a0, a1, a2, a3, aaddr);
#pragma unroll
        for (int hn = 0; hn < 2; hn++) {
            uint32_t bb0, bb1, bb2, bb3;
            uint32_t baddr = (uint32_t)__cvta_generic_to_shared(
                &ws_h[kk * 16 + brsub][wc * 32 + hn * 16 + bcsub]);
            LDSM_X4_T(bb0, bb1, bb2, bb3, baddr);
            MMA16816(c[hn*2][0], c[hn*2][1], c[hn*2][2], c[hn*2][3],
                     a0, a1, a2, a3, bb0, bb1);
            MMA16816(c[hn*2+1][0], c[hn*2+1][1], c[hn*2+1][2], c[hn*2+1][3],
                     a0, a1, a2, a3, bb2, bb3);
        }
    }

    // ---- epilogue: bias + relu + scale + fp16 store ----
    int r0 = base + wr * 16 + g;
    int r1 = r0 + 8;
    float sc0 = 1.f, sc1 = 1.f;
    if (!last) {
        if (r0 < N) sc0 = g_dinv[r0];
        if (r1 < N) sc1 = g_dinv[r1];
    }
#pragma unroll
    for (int ns = 0; ns < 4; ns++) {
        int col = wc * 32 + ns * 8 + 2 * tt;
        float bx = bcs[col], by = bcs[col + 1];
        if (r0 < N) {
            float vx = fmaxf(c[ns][0] + bx, 0.f) * sc0;
            float vy = fmaxf(c[ns][1] + by, 0.f) * sc0;
            dst[(size_t)r0 * 32 + (col >> 1)] = __floats2half2_rn(vx, vy);
        }
        if (r1 < N) {
            float vx = fmaxf(c[ns][2] + bx, 0.f) * sc1;
            float vy = fmaxf(c[ns][3] + by, 0.f) * sc1;
            dst[(size_t)r1 * 32 + (col >> 1)] = __floats2half2_rn(vx, vy);
        }
    }
}

// ---------------- Set2Set ----------------
__global__ void k_gates(int B) {
    int t = threadIdx.x;   // 256
    int gb = blockIdx.x * 16;
    __shared__ float xs[16][193];
    for (int id = t; id < 16 * 192; id += 256) {
        int g = id / 192, k = id % 192;
        int gg = gb + g;
        float v = 0.f;
        if (gg < B) v = (k < 128) ? g_qstar[gg * 128 + k] : g_hl[gg * 64 + (k - 128)];
        xs[g][k] = v;
    }
    __syncthreads();

    float acc[16];
#pragma unroll
    for (int g = 0; g < 16; g++) acc[g] = 0.f;
#pragma unroll 4
    for (int k = 0; k < 192; k++) {
        float wv = g_wT[k * 256 + t];
#pragma unroll
        for (int g = 0; g < 16; g++) acc[g] += xs[g][k] * wv;
    }
    __shared__ float gsh[256][17];
    float bsum = g_bsum[t];
#pragma unroll
    for (int g = 0; g < 16; g++) gsh[t][g] = acc[g] + bsum;
    __syncthreads();

    if (t < 64) {
        int j = t;
        for (int g = 0; g < 16; g++) {
            int gg = gb + g;
            if (gg >= B) break;
            float ig = sigmoidf(gsh[       j][g]);
            float fg = sigmoidf(gsh[ 64 + j][g]);
            float gv = tanhf   (gsh[128 + j][g]);
            float og = sigmoidf(gsh[192 + j][g]);
            int gi = gg * 64 + j;
            float cv = fg * g_cl[gi] + ig * gv;
            g_cl[gi] = cv;
            g_hl[gi] = og * tanhf(cv);
        }
    }
}

__global__ void k_attn(int N) {
    int b = blockIdx.x, tid = threadIdx.x;
    int wrp = tid >> 5, lane = tid & 31;
    int st = g_start[b];
    int cnt = g_gcnt[b];
    __shared__ float red[256];
    __shared__ float m_s, denom_s;

    // phase 0: e[n] = dot(feat[n], h_l[b])
    float2 qv = *(const float2*)&g_hl[b * 64 + lane * 2];
    for (int i = wrp; i < cnt; i += 8) {
        int n = st + i;
        float2 ov = __half22float2(g_h0[(size_t)n * 32 + lane]);
        float s = ov.x * qv.x + ov.y * qv.y;
#pragma unroll
        for (int o = 16; o; o >>= 1) s += __shfl_xor_sync(0xffffffffu, s, o);
        if (lane == 0) g_e[n] = s;
    }
    __syncthreads();

    // phase 1: max
    float local = -INFINITY;
    for (int i = tid; i < cnt; i += 256) local = fmaxf(local, g_e[st + i]);
    red[tid] = local;
    __syncthreads();
    if (tid < 128) red[tid] = fmaxf(red[tid], red[tid + 128]);
    __syncthreads();
    if (tid < 64) red[tid] = fmaxf(red[tid], red[tid + 64]);
    __syncthreads();
    if (tid < 32) {
        float v = fmaxf(red[tid], red[tid + 32]);
#pragma unroll
        for (int o = 16; o; o >>= 1) v = fmaxf(v, __shfl_xor_sync(0xffffffffu, v, o));
        if (tid == 0) m_s = v;
    }
    __syncthreads();
    float m = m_s;

    // phase 2: a = exp(e - m), denom
    float ls = 0.f;
    for (int i = tid; i < cnt; i += 256) {
        float a = expf(g_e[st + i] - m);
        g_e[st + i] = a;
        ls += a;
    }
    red[tid] = ls;
    __syncthreads();
    if (tid < 128) red[tid] += red[tid + 128];
    __syncthreads();
    if (tid < 64) red[tid] += red[tid + 64];
    __syncthreads();
    if (tid < 32) {
        float v = red[tid] + red[tid + 32];
#pragma unroll
        for (int o = 16; o; o >>= 1) v += __shfl_xor_sync(0xffffffffu, v, o);
        if (tid == 0) denom_s = v;
    }
    __syncthreads();
    float inv = (denom_s > 0.f) ? (1.0f / denom_s) : 0.f;

    // phase 3: r = sum a*out (fp16 features; 4 parallel 64-node groups)
    int grp = tid >> 6, c = tid & 63;
    const __half* featH = (const __half*)g_h0;
    float rc = 0.f;
    __shared__ float coeff[256];
    for (int base = 0; base < cnt; base += 256) {
        int i = base + tid;
        coeff[tid] = (i < cnt) ? g_e[st + i] * inv : 0.f;
        __syncthreads();
        int off = base + grp * 64;
        int lim = cnt - off; if (lim > 64) lim = 64;
        const __half* srcp = featH + (size_t)(st + off) * 64 + c;
        for (int j = 0; j < lim; j++) {
            rc += coeff[grp * 64 + j] * __half2float(srcp[(size_t)j * 64]);
        }
        __syncthreads();
    }
    red[tid] = rc;
    __syncthreads();
    if (tid < 64) {
        float r = red[tid] + red[tid + 64] + red[tid + 128] + red[tid + 192];
        g_qstar[b * 128 + tid]      = g_hl[b * 64 + tid];
        g_qstar[b * 128 + 64 + tid] = r;
    }
}

__global__ void k_final(const float* __restrict__ W1, const float* __restrict__ b1,
                        const float* __restrict__ W2, const float* __restrict__ b2,
                        float* __restrict__ y) {
    int b = blockIdx.x, t = threadIdx.x;  // 64 threads
    __shared__ float qs[128];
    __shared__ float hid[64];
    qs[t]      = g_qstar[b * 128 + t];
    qs[t + 64] = g_qstar[b * 128 + 64 + t];
    __syncthreads();
    float acc = b1[t];
#pragma unroll 8
    for (int k = 0; k < 128; k++) acc += qs[k] * W1[k * 64 + t];
    hid[t] = fmaxf(acc, 0.f);
    __syncthreads();
    if (t < 12) {
        float a = b2[t];
#pragma unroll 8
        for (int k = 0; k < 64; k++) a += hid[k] * W2[k * 12 + t];
        y[b * 12 + t] = a;
    }
}

// ---------------- launch ----------------
extern "C" void kernel_launch(void* const* d_in, const int* in_sizes, int n_in,
                              void* d_out, int out_size) {
    const float* x     = (const float*)d_in[0];
    const int*   ei    = (const int*)  d_in[1];
    const int*   batch = (const int*)  d_in[2];
    const float* W0    = (const float*)d_in[3];
    const float* b0    = (const float*)d_in[4];
    const float* Wc    = (const float*)d_in[5];
    const float* bc    = (const float*)d_in[6];
    const float* Wih   = (const float*)d_in[7];
    const float* Whh   = (const float*)d_in[8];
    const float* bih   = (const float*)d_in[9];
    const float* bhh   = (const float*)d_in[10];
    const float* W1    = (const float*)d_in[11];
    const float* b1    = (const float*)d_in[12];
    const float* W2    = (const float*)d_in[13];
    const float* b2    = (const float*)d_in[14];
    float* y = (float*)d_out;

    int N = in_sizes[0] / 15;
    int E = in_sizes[1] / 2;
    int B = out_size / 12;

    // ---- init + build ----
    int zmax = (N > B * 2 * D) ? N : B * 2 * D;
    k_zero<<<(zmax + 255) / 256, 256>>>(N, B);
    k_build<<<(E + 255) / 256, 256>>>(ei, E);
    k_boundary<<<(N + 255) / 256, 256>>>(batch, N);
    k_wT<<<(192 * 256 + 255) / 256, 256>>>(Wih, Whh, bih, bhh);
    k_dinv<<<(N + 255) / 256, 256>>>(N);
    k_init_feat<<<(N * 32 + 255) / 256, 256>>>(x, W0, b0, N);

    // ---- 6 fused propagation steps ----
    for (int s = 0; s < 6; s++) {
        k_prop<<<(N + 63) / 64, 256>>>(Wc, bc, N, s & 1, (s == 5) ? 1 : 0);
    }

    // ---- Set2Set ----
    for (int s = 0; s < 6; s++) {
        k_gates<<<(B + 15) / 16, 256>>>(B);
        k_attn<<<B, 256>>>(N);
    }

    // ---- final MLP ----
    k_final<<<B, 64>>>(W1, b1, W2, b2, y);
}

// round 9
// speedup vs baseline: 1.6347x; 1.1304x over previous
#include <cuda_runtime.h>
#include <cuda_fp16.h>
#include <stdint.h>
#include <math.h>

#define D      64
#define CAP    128           // max in-degree slots (Poisson(32): P(>=128) ~ e^-81)
#define MAXN   100000
#define MAXB   1024

// ---------------- static device scratch ----------------
__device__ __half2 g_h0[MAXN * 32];       // fp16 node features (scaled by dinv), ping
__device__ __half2 g_h1[MAXN * 32];       // pong
__device__ int     g_cnt[MAXN];
__device__ int     g_csr_row[MAXN * CAP];
__device__ float   g_dinv[MAXN];
__device__ float   g_e[MAXN];
__device__ int     g_start[MAXB];
__device__ int     g_gcnt[MAXB];
__device__ float   g_hl[MAXB * D];
__device__ float   g_cl[MAXB * D];
__device__ float   g_qstar[MAXB * 2 * D];
__device__ float   g_wT[192 * 256];       // transposed [Wih|Whh]: wT[k][out]
__device__ float   g_bsum[256];           // bih + bhh
__device__ __half  g_wc16[64 * 64];       // Wc in fp16, row-major [k][n]

__device__ __forceinline__ float sigmoidf(float x) { return 1.0f / (1.0f + expf(-x)); }

#define LDSM_X4(r0,r1,r2,r3, addr) \
  asm volatile("ldmatrix.sync.aligned.m8n8.x4.shared.b16 {%0,%1,%2,%3}, [%4];" \
    : "=r"(r0), "=r"(r1), "=r"(r2), "=r"(r3) : "r"(addr))

#define LDSM_X4_T(r0,r1,r2,r3, addr) \
  asm volatile("ldmatrix.sync.aligned.m8n8.x4.trans.shared.b16 {%0,%1,%2,%3}, [%4];" \
    : "=r"(r0), "=r"(r1), "=r"(r2), "=r"(r3) : "r"(addr))

#define MMA16816(c0,c1,c2,c3, a0,a1,a2,a3, b0,b1) \
  asm volatile("mma.sync.aligned.m16n8k16.row.col.f32.f16.f16.f32 " \
    "{%0,%1,%2,%3}, {%4,%5,%6,%7}, {%8,%9}, {%0,%1,%2,%3};" \
    : "+f"(c0), "+f"(c1), "+f"(c2), "+f"(c3) \
    : "r"(a0), "r"(a1), "r"(a2), "r"(a3), "r"(b0), "r"(b1))

// ---------------- init / build ----------------
__global__ void k_zero(int N, int B) {
    int i = blockIdx.x * blockDim.x + threadIdx.x;
    if (i < N) g_cnt[i] = 0;
    if (i < B) { g_start[i] = N; g_gcnt[i] = 0; }
    if (i < B * D) { g_hl[i] = 0.f; g_cl[i] = 0.f; }
    if (i < B * 2 * D) g_qstar[i] = 0.f;
}

__global__ void k_build(const int* __restrict__ ei, int E) {
    int e = blockIdx.x * blockDim.x + threadIdx.x;
    if (e >= E) return;
    int r = ei[e];
    int c = ei[E + e];
    int slot = atomicAdd(&g_cnt[c], 1);
    if (slot < CAP) g_csr_row[c * CAP + slot] = r;
}

__global__ void k_dinv(int N) {
    int n = blockIdx.x * blockDim.x + threadIdx.x;
    if (n >= N) return;
    float deg = (float)(g_cnt[n] + 1);
    g_dinv[n] = rsqrtf(deg);
}

// out0 = dinv * relu(x @ W0 + b0) -> fp16 ping buffer (pre-scaled storage)
__global__ void k_init_feat(const float* __restrict__ x, const float* __restrict__ W0,
                            const float* __restrict__ b0, int N) {
    int idx = blockIdx.x * blockDim.x + threadIdx.x;
    if (idx >= N * 32) return;
    int n = idx >> 5, p = idx & 31;
    int c0 = 2 * p;
    float a0 = b0[c0], a1 = b0[c0 + 1];
    const float* xr = x + n * 15;
#pragma unroll
    for (int k = 0; k < 15; k++) {
        float xv = xr[k];
        a0 += xv * W0[k * D + c0];
        a1 += xv * W0[k * D + c0 + 1];
    }
    float dv = g_dinv[n];
    g_h0[idx] = __floats2half2_rn(dv * fmaxf(a0, 0.f), dv * fmaxf(a1, 0.f));
}

// transpose LSTM weights + convert Wc to fp16
__global__ void k_wT(const float* __restrict__ Wih, const float* __restrict__ Whh,
                     const float* __restrict__ bih, const float* __restrict__ bhh,
                     const float* __restrict__ Wc) {
    int idx = blockIdx.x * blockDim.x + threadIdx.x;
    if (idx < 64 * 64) g_wc16[idx] = __float2half(Wc[idx]);
    if (idx >= 192 * 256) return;
    int k = idx >> 8, o = idx & 255;
    float v = (k < 128) ? Wih[o * 128 + k] : Whh[o * 64 + (k - 128)];
    g_wT[k * 256 + o] = v;
    if (k == 0) g_bsum[o] = bih[o] + bhh[o];
}

__global__ void k_boundary(const int* __restrict__ batch, int N) {
    int n = blockIdx.x * blockDim.x + threadIdx.x;
    if (n >= N) return;
    int bn = batch[n];
    if (n == 0 || batch[n - 1] != bn) g_start[bn] = n;
    atomicAdd(&g_gcnt[bn], 1);
}

// ---------------- fused propagation: gather(fp16) -> HMMA GEMM -> fp16 ----
// features pre-scaled: f = dinv*out ; agg = sum f_r + f_self ; x = dinv*agg
// out = relu(x @ Wc + bc) ; store last ? out : dinv*out
__global__ void k_prop(const float* __restrict__ bc, int N, int flip, int last) {
    const __half2* __restrict__ src = flip ? g_h1 : g_h0;
    __half2*       __restrict__ dst = flip ? g_h0 : g_h1;
    __shared__ __half xs_h[64][72];    // gathered x tile (fp16), ldmatrix-friendly
    __shared__ __half ws_h[64][72];    // Wc fp16 [k][n]
    __shared__ float  bcs[64];
    int t = threadIdx.x;               // 256 threads
    int base = blockIdx.x * 64;
    int wrp = t >> 5, lane = t & 31;

    if (t < 64) bcs[t] = bc[t];
    // copy Wc fp16 (8 KB) via uint4: 512 vectors, 2 per thread
    {
        const uint4* wsrc = (const uint4*)g_wc16;
#pragma unroll
        for (int i = t; i < 512; i += 256) {
            int row = i >> 3, c8 = (i & 7) << 3;
            *(uint4*)&ws_h[row][c8] = wsrc[i];
        }
    }

    // gather: warp wrp handles local rows wrp*8 .. wrp*8+7 (weight-free sum)
#pragma unroll 1
    for (int q = 0; q < 8; q++) {
        int row = wrp * 8 + q;
        int n = base + row;
        float ax = 0.f, ay = 0.f;
        if (n < N) {
            int cnt = g_cnt[n]; if (cnt > CAP) cnt = CAP;
            const int* rows = &g_csr_row[n * CAP];
            int s8 = cnt & ~7;
            if (s8) {
                // software-pipelined: prefetch next indices before add tree
                int4 ra = *(const int4*)(rows);
                int4 rb = *(const int4*)(rows + 4);
                for (int s = 8; ; s += 8) {
                    int4 ra_n, rb_n;
                    if (s < s8) {
                        ra_n = *(const int4*)(rows + s);
                        rb_n = *(const int4*)(rows + s + 4);
                    }
                    __half2 h0 = src[ra.x * 32 + lane];
                    __half2 h1 = src[ra.y * 32 + lane];
                    __half2 h2 = src[ra.z * 32 + lane];
                    __half2 h3 = src[ra.w * 32 + lane];
                    __half2 h4 = src[rb.x * 32 + lane];
                    __half2 h5 = src[rb.y * 32 + lane];
                    __half2 h6 = src[rb.z * 32 + lane];
                    __half2 h7 = src[rb.w * 32 + lane];
                    __half2 t0 = __hadd2(h0, h1);
                    __half2 t1 = __hadd2(h2, h3);
                    __half2 t2 = __hadd2(h4, h5);
                    __half2 t3 = __hadd2(h6, h7);
                    t0 = __hadd2(t0, t1);
                    t2 = __hadd2(t2, t3);
                    t0 = __hadd2(t0, t2);
                    float2 f = __half22float2(t0);
                    ax += f.x; ay += f.y;
                    if (s >= s8) break;
                    ra = ra_n; rb = rb_n;
                }
            }
            int s = s8;
            if (s + 4 <= cnt) {
                int4 ra = *(const int4*)(rows + s);
                __half2 h0 = src[ra.x * 32 + lane];
                __half2 h1 = src[ra.y * 32 + lane];
                __half2 h2 = src[ra.z * 32 + lane];
                __half2 h3 = src[ra.w * 32 + lane];
                __half2 t0 = __hadd2(__hadd2(h0, h1), __hadd2(h2, h3));
                float2 f = __half22float2(t0);
                ax += f.x; ay += f.y;
                s += 4;
            }
            for (; s < cnt; s++) {
                float2 f = __half22float2(src[rows[s] * 32 + lane]);
                ax += f.x; ay += f.y;
            }
            float2 hs = __half22float2(src[n * 32 + lane]);
            float dv = g_dinv[n];
            ax = dv * (ax + hs.x);
            ay = dv * (ay + hs.y);
        }
        *(__half2*)&xs_h[row][lane * 2] = __floats2half2_rn(ax, ay);
    }
    __syncthreads();

    // ---- HMMA GEMM: C(64x64) = xs_h @ ws_h, warp tile 16x32 ----
    int wr = wrp >> 1;        // row group 0..3 (16 rows each)
    int wc = wrp & 1;         // col group 0..1 (32 cols each)
    int g  = lane >> 2;       // group id 0..7
    int tt = lane & 3;        // thread in group

    float c[4][4];
#pragma unroll
    for (int i = 0; i < 4; i++)
#pragma unroll
        for (int j = 0; j < 4; j++) c[i][j] = 0.f;

    int arow = wr * 16 + ((lane >> 3) & 1) * 8 + (lane & 7);
    int asub = (lane >> 4) * 8;
    int brsub = ((lane >> 3) & 1) * 8 + (lane & 7);
    int bcsub = (lane >> 4) * 8;

#pragma unroll
    for (int kk = 0; kk < 4; kk++) {
        uint32_t a0, a1, a2, a3;
        uint32_t aaddr = (uint32_t)__cvta_generic_to_shared(&xs_h[arow][kk * 16 + asub]);
        LDSM_X4(a0, a1, a2, a3, aaddr);
#pragma unroll
        for (int hn = 0; hn < 2; hn++) {
            uint32_t bb0, bb1, bb2, bb3;
            uint32_t baddr = (uint32_t)__cvta_generic_to_shared(
                &ws_h[kk * 16 + brsub][wc * 32 + hn * 16 + bcsub]);
            LDSM_X4_T(bb0, bb1, bb2, bb3, baddr);
            MMA16816(c[hn*2][0], c[hn*2][1], c[hn*2][2], c[hn*2][3],
                     a0, a1, a2, a3, bb0, bb1);
            MMA16816(c[hn*2+1][0], c[hn*2+1][1], c[hn*2+1][2], c[hn*2+1][3],
                     a0, a1, a2, a3, bb2, bb3);
        }
    }

    // ---- epilogue: bias + relu + scale + fp16 store ----
    int r0 = base + wr * 16 + g;
    int r1 = r0 + 8;
    float sc0 = 1.f, sc1 = 1.f;
    if (!last) {
        if (r0 < N) sc0 = g_dinv[r0];
        if (r1 < N) sc1 = g_dinv[r1];
    }
#pragma unroll
    for (int ns = 0; ns < 4; ns++) {
        int col = wc * 32 + ns * 8 + 2 * tt;
        float bx = bcs[col], by = bcs[col + 1];
        if (r0 < N) {
            float vx = fmaxf(c[ns][0] + bx, 0.f) * sc0;
            float vy = fmaxf(c[ns][1] + by, 0.f) * sc0;
            dst[(size_t)r0 * 32 + (col >> 1)] = __floats2half2_rn(vx, vy);
        }
        if (r1 < N) {
            float vx = fmaxf(c[ns][2] + bx, 0.f) * sc1;
            float vy = fmaxf(c[ns][3] + by, 0.f) * sc1;
            dst[(size_t)r1 * 32 + (col >> 1)] = __floats2half2_rn(vx, vy);
        }
    }
}

// ---------------- Set2Set ----------------
__global__ void k_gates(int B) {
    int t = threadIdx.x;   // 256
    int gb = blockIdx.x * 16;
    __shared__ float xs[16][193];
    for (int id = t; id < 16 * 192; id += 256) {
        int g = id / 192, k = id % 192;
        int gg = gb + g;
        float v = 0.f;
        if (gg < B) v = (k < 128) ? g_qstar[gg * 128 + k] : g_hl[gg * 64 + (k - 128)];
        xs[g][k] = v;
    }
    __syncthreads();

    float acc[16];
#pragma unroll
    for (int g = 0; g < 16; g++) acc[g] = 0.f;
#pragma unroll 4
    for (int k = 0; k < 192; k++) {
        float wv = g_wT[k * 256 + t];
#pragma unroll
        for (int g = 0; g < 16; g++) acc[g] += xs[g][k] * wv;
    }
    __shared__ float gsh[256][17];
    float bsum = g_bsum[t];
#pragma unroll
    for (int g = 0; g < 16; g++) gsh[t][g] = acc[g] + bsum;
    __syncthreads();

    if (t < 64) {
        int j = t;
        for (int g = 0; g < 16; g++) {
            int gg = gb + g;
            if (gg >= B) break;
            float ig = sigmoidf(gsh[       j][g]);
            float fg = sigmoidf(gsh[ 64 + j][g]);
            float gv = tanhf   (gsh[128 + j][g]);
            float og = sigmoidf(gsh[192 + j][g]);
            int gi = gg * 64 + j;
            float cv = fg * g_cl[gi] + ig * gv;
            g_cl[gi] = cv;
            g_hl[gi] = og * tanhf(cv);
        }
    }
}

__global__ void k_attn(int N) {
    int b = blockIdx.x, tid = threadIdx.x;
    int wrp = tid >> 5, lane = tid & 31;
    int st = g_start[b];
    int cnt = g_gcnt[b];
    __shared__ float red[256];
    __shared__ float m_s, denom_s;

    // phase 0: e[n] = dot(feat[n], h_l[b])
    float2 qv = *(const float2*)&g_hl[b * 64 + lane * 2];
    for (int i = wrp; i < cnt; i += 8) {
        int n = st + i;
        float2 ov = __half22float2(g_h0[(size_t)n * 32 + lane]);
        float s = ov.x * qv.x + ov.y * qv.y;
#pragma unroll
        for (int o = 16; o; o >>= 1) s += __shfl_xor_sync(0xffffffffu, s, o);
        if (lane == 0) g_e[n] = s;
    }
    __syncthreads();

    // phase 1: max
    float local = -INFINITY;
    for (int i = tid; i < cnt; i += 256) local = fmaxf(local, g_e[st + i]);
    red[tid] = local;
    __syncthreads();
    if (tid < 128) red[tid] = fmaxf(red[tid], red[tid + 128]);
    __syncthreads();
    if (tid < 64) red[tid] = fmaxf(red[tid], red[tid + 64]);
    __syncthreads();
    if (tid < 32) {
        float v = fmaxf(red[tid], red[tid + 32]);
#pragma unroll
        for (int o = 16; o; o >>= 1) v = fmaxf(v, __shfl_xor_sync(0xffffffffu, v, o));
        if (tid == 0) m_s = v;
    }
    __syncthreads();
    float m = m_s;

    // phase 2: a = exp(e - m), denom
    float ls = 0.f;
    for (int i = tid; i < cnt; i += 256) {
        float a = expf(g_e[st + i] - m);
        g_e[st + i] = a;
        ls += a;
    }
    red[tid] = ls;
    __syncthreads();
    if (tid < 128) red[tid] += red[tid + 128];
    __syncthreads();
    if (tid < 64) red[tid] += red[tid + 64];
    __syncthreads();
    if (tid < 32) {
        float v = red[tid] + red[tid + 32];
#pragma unroll
        for (int o = 16; o; o >>= 1) v += __shfl_xor_sync(0xffffffffu, v, o);
        if (tid == 0) denom_s = v;
    }
    __syncthreads();
    float inv = (denom_s > 0.f) ? (1.0f / denom_s) : 0.f;

    // phase 3: r = sum a*out (fp16 features; 4 parallel 64-node groups)
    int grp = tid >> 6, c = tid & 63;
    const __half* featH = (const __half*)g_h0;
    float rc = 0.f;
    __shared__ float coeff[256];
    for (int base = 0; base < cnt; base += 256) {
        int i = base + tid;
        coeff[tid] = (i < cnt) ? g_e[st + i] * inv : 0.f;
        __syncthreads();
        int off = base + grp * 64;
        int lim = cnt - off; if (lim > 64) lim = 64;
        const __half* srcp = featH + (size_t)(st + off) * 64 + c;
        for (int j = 0; j < lim; j++) {
            rc += coeff[grp * 64 + j] * __half2float(srcp[(size_t)j * 64]);
        }
        __syncthreads();
    }
    red[tid] = rc;
    __syncthreads();
    if (tid < 64) {
        float r = red[tid] + red[tid + 64] + red[tid + 128] + red[tid + 192];
        g_qstar[b * 128 + tid]      = g_hl[b * 64 + tid];
        g_qstar[b * 128 + 64 + tid] = r;
    }
}

__global__ void k_final(const float* __restrict__ W1, const float* __restrict__ b1,
                        const float* __restrict__ W2, const float* __restrict__ b2,
                        float* __restrict__ y) {
    int b = blockIdx.x, t = threadIdx.x;  // 64 threads
    __shared__ float qs[128];
    __shared__ float hid[64];
    qs[t]      = g_qstar[b * 128 + t];
    qs[t + 64] = g_qstar[b * 128 + 64 + t];
    __syncthreads();
    float acc = b1[t];
#pragma unroll 8
    for (int k = 0; k < 128; k++) acc += qs[k] * W1[k * 64 + t];
    hid[t] = fmaxf(acc, 0.f);
    __syncthreads();
    if (t < 12) {
        float a = b2[t];
#pragma unroll 8
        for (int k = 0; k < 64; k++) a += hid[k] * W2[k * 12 + t];
        y[b * 12 + t] = a;
    }
}

// ---------------- launch ----------------
extern "C" void kernel_launch(void* const* d_in, const int* in_sizes, int n_in,
                              void* d_out, int out_size) {
    const float* x     = (const float*)d_in[0];
    const int*   ei    = (const int*)  d_in[1];
    const int*   batch = (const int*)  d_in[2];
    const float* W0    = (const float*)d_in[3];
    const float* b0    = (const float*)d_in[4];
    const float* Wc    = (const float*)d_in[5];
    const float* bc    = (const float*)d_in[6];
    const float* Wih   = (const float*)d_in[7];
    const float* Whh   = (const float*)d_in[8];
    const float* bih   = (const float*)d_in[9];
    const float* bhh   = (const float*)d_in[10];
    const float* W1    = (const float*)d_in[11];
    const float* b1    = (const float*)d_in[12];
    const float* W2    = (const float*)d_in[13];
    const float* b2    = (const float*)d_in[14];
    float* y = (float*)d_out;

    int N = in_sizes[0] / 15;
    int E = in_sizes[1] / 2;
    int B = out_size / 12;

    // ---- init + build ----
    int zmax = (N > B * 2 * D) ? N : B * 2 * D;
    k_zero<<<(zmax + 255) / 256, 256>>>(N, B);
    k_build<<<(E + 255) / 256, 256>>>(ei, E);
    k_boundary<<<(N + 255) / 256, 256>>>(batch, N);
    k_wT<<<(192 * 256 + 255) / 256, 256>>>(Wih, Whh, bih, bhh, Wc);
    k_dinv<<<(N + 255) / 256, 256>>>(N);
    k_init_feat<<<(N * 32 + 255) / 256, 256>>>(x, W0, b0, N);

    // ---- 6 fused propagation steps ----
    for (int s = 0; s < 6; s++) {
        k_prop<<<(N + 63) / 64, 256>>>(bc, N, s & 1, (s == 5) ? 1 : 0);
    }

    // ---- Set2Set ----
    for (int s = 0; s < 6; s++) {
        k_gates<<<(B + 15) / 16, 256>>>(B);
        k_attn<<<B, 256>>>(N);
    }

    // ---- final MLP ----
    k_final<<<B, 64>>>(W1, b1, W2, b2, y);
}